// round 12
// baseline (speedup 1.0000x reference)
#include <cuda_runtime.h>
#include <cuda_bf16.h>
#include <cuda_fp16.h>
#include <math.h>
#include <stdint.h>

#define NN 50000
#define EE 200000
#define E2 (EE + NN)
#define HD 128

// ---------------- scratch (static device globals; no allocation) ----------------
__device__ int   g_down[NN];
__device__ __align__(16) __half g_hh[NN * HD];
__device__ __align__(16) __half g_hh2[NN * HD];
__device__ __align__(16) __half g_aggh[(size_t)NN * 512];
__device__ __align__(16) float g_als[NN * 4];
__device__ __align__(16) float g_ald[NN * 4];
__device__ int   g_cnt[NN];
__device__ int   g_rowtmp[NN];
__device__ int   g_bsum[64];
__device__ int   g_rowptr[NN + 1];
__device__ int   g_cursor[NN];
__device__ int   g_csrsrc[E2];
__device__ __align__(16) __half g_pqh[2 * (size_t)NN * HD];  // p then q
__device__ __align__(16) float g_wsrc[3 * 4 * 128];
__device__ __align__(16) float g_wdst[3 * 4 * 128];
__device__ __align__(16) __half g_wpermh[3 * 128 * 512];  // [l][cout][kk]
__device__ __align__(16) __half g_empq[2 * 128 * 128];    // [n][k] p-half then q-half
__device__ __align__(16) __half g_emw2h[64 * 128];        // [n][k]
__device__ __align__(16) float g_bnscale[3 * 128];
__device__ __align__(16) float g_bnshift[3 * 128];

__device__ __forceinline__ uint32_t f22u(float a, float b) {
    __half2 h = __floats2half2_rn(a, b);
    return *(uint32_t*)&h;
}
__device__ __forceinline__ float4 u2tof4(uint2 u) {
    float2 a = __half22float2(*(__half2*)&u.x);
    float2 b = __half22float2(*(__half2*)&u.y);
    return make_float4(a.x, a.y, b.x, b.y);
}

// ---------------- small helpers ----------------
__global__ void k_zero_misc() {
    int i = blockIdx.x * blockDim.x + threadIdx.x;
    if (i < NN) { g_down[i] = 0; g_cnt[i] = 0; }
}

__global__ void k_downcount(const int* __restrict__ src, const int* __restrict__ dst,
                            const int* __restrict__ shock) {
    int e = blockIdx.x * blockDim.x + threadIdx.x;
    if (e >= E2) return;
    if (e < EE) {
        int s = src[e], d = dst[e];
        if (shock[s] != 0) g_down[d] = 1;
        atomicAdd(&g_cnt[d], 1);
    } else {
        atomicAdd(&g_cnt[e - EE], 1);
    }
}

__global__ void k_scan1() {
    __shared__ int sh[1024];
    int tid = threadIdx.x;
    int i = blockIdx.x * 1024 + tid;
    int v = (i < NN) ? g_cnt[i] : 0;
    sh[tid] = v;
    __syncthreads();
    for (int off = 1; off < 1024; off <<= 1) {
        int t = (tid >= off) ? sh[tid - off] : 0;
        __syncthreads();
        sh[tid] += t;
        __syncthreads();
    }
    int incl = sh[tid];
    if (i < NN) g_rowtmp[i] = incl - v;
    if (tid == 1023) g_bsum[blockIdx.x] = incl;
}

// parallel exclusive scan over <=64 block sums
__global__ void k_scan2(int nb) {
    __shared__ int sh[64];
    int t = threadIdx.x;
    int v = (t < nb) ? g_bsum[t] : 0;
    sh[t] = v;
    __syncthreads();
    for (int off = 1; off < 64; off <<= 1) {
        int u = (t >= off) ? sh[t - off] : 0;
        __syncthreads();
        sh[t] += u;
        __syncthreads();
    }
    if (t < nb) g_bsum[t] = sh[t] - v;
}

__global__ void k_scan3() {
    int i = blockIdx.x * blockDim.x + threadIdx.x;
    if (i >= NN) return;
    int r = g_rowtmp[i] + g_bsum[i >> 10];
    g_rowptr[i] = r;
    g_cursor[i] = r;
    if (i == NN - 1) g_rowptr[NN] = E2;
}

__global__ void k_scatter(const int* __restrict__ src, const int* __restrict__ dst) {
    int e = blockIdx.x * blockDim.x + threadIdx.x;
    if (e >= E2) return;
    int s, d;
    if (e < EE) { s = src[e]; d = dst[e]; } else { s = e - EE; d = e - EE; }
    int pos = atomicAdd(&g_cursor[d], 1);
    g_csrsrc[pos] = s;
}

// ---------------- node encoder: 64 nodes/block, W in smem, warp-per-node, fp16 out ----
__global__ __launch_bounds__(256) void k_encoder2(
        const float* __restrict__ x, const int* __restrict__ shock,
        const float* __restrict__ W, const float* __restrict__ b,
        const float* __restrict__ lng, const float* __restrict__ lnb,
        __half* __restrict__ hout) {
    __shared__ __align__(16) float Ws[18][128];
    __shared__ __align__(16) float bs[128], gs[128], os[128];
    int tid = threadIdx.x;
#pragma unroll
    for (int i = 0; i < 3; i++) {
        int idx = tid + i * 256;
        if (idx < 576) ((float4*)Ws)[idx] = ((const float4*)W)[idx];
    }
    if (tid < 128) { bs[tid] = b[tid]; gs[tid] = lng[tid]; os[tid] = lnb[tid]; }
    __syncthreads();

    int w = tid >> 5, lane = tid & 31;
#pragma unroll
    for (int it = 0; it < 8; it++) {
        int n = blockIdx.x * 64 + it * 8 + w;
        if (n >= NN) continue;
        const float4* xr = (const float4*)(x + n * 16);
        float4 x0 = xr[0], x1 = xr[1], x2 = xr[2], x3 = xr[3];
        float sh_ = (float)shock[n];
        float dn_ = (float)g_down[n];
        float xa[16] = {x0.x, x0.y, x0.z, x0.w, x1.x, x1.y, x1.z, x1.w,
                        x2.x, x2.y, x2.z, x2.w, x3.x, x3.y, x3.z, x3.w};
        int c = lane * 4;
        float4 v = *(const float4*)&bs[c];
#pragma unroll
        for (int j = 0; j < 16; j++) {
            float4 w4 = *(const float4*)&Ws[j][c];
            v.x += xa[j] * w4.x; v.y += xa[j] * w4.y;
            v.z += xa[j] * w4.z; v.w += xa[j] * w4.w;
        }
        {
            float4 w4 = *(const float4*)&Ws[16][c];
            v.x += sh_ * w4.x; v.y += sh_ * w4.y; v.z += sh_ * w4.z; v.w += sh_ * w4.w;
            float4 w5 = *(const float4*)&Ws[17][c];
            v.x += dn_ * w5.x; v.y += dn_ * w5.y; v.z += dn_ * w5.z; v.w += dn_ * w5.w;
        }
        float su = v.x + v.y + v.z + v.w;
        float sq = v.x * v.x + v.y * v.y + v.z * v.z + v.w * v.w;
#pragma unroll
        for (int off = 16; off > 0; off >>= 1) {
            su += __shfl_xor_sync(0xffffffffu, su, off);
            sq += __shfl_xor_sync(0xffffffffu, sq, off);
        }
        float mu = su * (1.0f / HD);
        float var = sq * (1.0f / HD) - mu * mu;
        float rs = rsqrtf(var + 1e-5f);
        float4 g4 = *(const float4*)&gs[c];
        float4 o4 = *(const float4*)&os[c];
        float y0 = fmaxf((v.x - mu) * rs * g4.x + o4.x, 0.0f);
        float y1 = fmaxf((v.y - mu) * rs * g4.y + o4.y, 0.0f);
        float y2 = fmaxf((v.z - mu) * rs * g4.z + o4.z, 0.0f);
        float y3 = fmaxf((v.w - mu) * rs * g4.w + o4.w, 0.0f);
        *(uint2*)&hout[(size_t)n * HD + c] = make_uint2(f22u(y0, y1), f22u(y2, y3));
    }
}

// ---------------- weight prep ----------------
__global__ void k_watt(const float* __restrict__ gw,
                       const float* __restrict__ as_, const float* __restrict__ ad_) {
    int l = blockIdx.x, h = blockIdx.y;
    int k = threadIdx.x;
    __shared__ float s_as[128], s_ad[128];
    s_as[k] = as_[(l * 4 + h) * 128 + k];
    s_ad[k] = ad_[(l * 4 + h) * 128 + k];
    __syncthreads();
    const float* wrow = gw + ((size_t)l * 128 + k) * 512 + h * 128;
    float ss = 0.0f, sd = 0.0f;
#pragma unroll 8
    for (int cc = 0; cc < 128; cc++) {
        float w = wrow[cc];
        ss += w * s_as[cc];
        sd += w * s_ad[cc];
    }
    g_wsrc[(l * 4 + h) * 128 + k] = ss;
    g_wdst[(l * 4 + h) * 128 + k] = sd;
}

__global__ void k_permw_h(const float* __restrict__ gw) {
    int l = blockIdx.x;
    int kk = blockIdx.y;
    int cout = threadIdx.x;
    int k_in = kk & 127, hd = kk >> 7;
    float v = 0.25f * gw[((size_t)l * 128 + k_in) * 512 + (hd << 7) + cout];
    g_wpermh[((size_t)l * 128 + cout) * 512 + kk] = __float2half(v);
}

__global__ void k_prep_em(const float* __restrict__ em1w, const float* __restrict__ em2w) {
    int n = blockIdx.x;
    int k = threadIdx.x;
    g_empq[n * 128 + k]               = __float2half(em1w[(size_t)k * 128 + n]);
    g_empq[128 * 128 + n * 128 + k]   = __float2half(em1w[(size_t)(128 + k) * 128 + n]);
    if (n < 64) g_emw2h[n * 128 + k]  = __float2half(em2w[(size_t)k * 64 + n]);
}

__global__ void k_bnprep(const float* __restrict__ bias, const float* __restrict__ bng,
                         const float* __restrict__ bnb, const float* __restrict__ bnm,
                         const float* __restrict__ bnv) {
    int l = blockIdx.x, c = threadIdx.x;
    int i = l * 128 + c;
    float sc = bng[i] * rsqrtf(bnv[i] + 1e-5f);
    g_bnscale[i] = sc;
    g_bnshift[i] = (bias[i] - bnm[i]) * sc + bnb[i];
}

// ---------------- fp16 tensor-core GEMM: C[M,128] = A[M,K] @ B^T ----------------
// A fp16 [M][K], B fp16 [128][K] selected by blockIdx.y*bStride, C fp16 (+bStride sel).
// Optional per-channel scale/shift (+relu) epilogue.
__device__ __forceinline__ void mma_f16(float* d, const uint32_t* a, const uint32_t* b) {
    asm volatile(
        "mma.sync.aligned.m16n8k16.row.col.f32.f16.f16.f32 "
        "{%0,%1,%2,%3}, {%4,%5,%6,%7}, {%8,%9}, {%0,%1,%2,%3};\n"
        : "+f"(d[0]), "+f"(d[1]), "+f"(d[2]), "+f"(d[3])
        : "r"(a[0]), "r"(a[1]), "r"(a[2]), "r"(a[3]), "r"(b[0]), "r"(b[1]));
}

__global__ __launch_bounds__(256) void gemm_f16(
        const __half* __restrict__ A, const __half* __restrict__ B0,
        __half* __restrict__ C0, int M, int K,
        const float* __restrict__ escale, const float* __restrict__ eshift,
        int do_relu, long bStride, long cStride) {
    __shared__ __align__(16) __half As[128][40];
    __shared__ __align__(16) __half Bs[128][40];
    const __half* B = B0 + blockIdx.y * bStride;
    __half* C = C0 + blockIdx.y * cStride;
    int tid = threadIdx.x;
    int m0 = blockIdx.x * 128;
    int lane = tid & 31, wid = tid >> 5;
    int mbase = (wid & 1) * 64;
    int nbase = (wid >> 1) * 32;
    int gid = lane >> 2, tg = lane & 3;

    float acc[4][4][4];
#pragma unroll
    for (int i = 0; i < 4; i++)
#pragma unroll
        for (int j = 0; j < 4; j++)
#pragma unroll
            for (int q = 0; q < 4; q++) acc[i][j][q] = 0.0f;

    for (int kc = 0; kc < K; kc += 32) {
        __syncthreads();
#pragma unroll
        for (int i = 0; i < 2; i++) {
            int l4 = tid + i * 256;
            int row = l4 >> 2, c8 = (l4 & 3) << 3;
            uint4 v = make_uint4(0, 0, 0, 0);
            int gr = m0 + row;
            if (gr < M) v = *(const uint4*)&A[(size_t)gr * K + kc + c8];
            *(uint4*)&As[row][c8] = v;
        }
#pragma unroll
        for (int i = 0; i < 2; i++) {
            int l = tid + i * 256;
            int n = l >> 2, k8 = (l & 3) << 3;
            uint4 v = *(const uint4*)&B[(size_t)n * K + kc + k8];
            *(uint4*)&Bs[n][k8] = v;
        }
        __syncthreads();

#pragma unroll
        for (int k0 = 0; k0 < 32; k0 += 16) {
            uint32_t af[4][4], bf[4][2];
#pragma unroll
            for (int am = 0; am < 4; am++) {
                int row0 = mbase + am * 16 + gid;
                af[am][0] = *(const uint32_t*)&As[row0][k0 + tg * 2];
                af[am][1] = *(const uint32_t*)&As[row0 + 8][k0 + tg * 2];
                af[am][2] = *(const uint32_t*)&As[row0][k0 + tg * 2 + 8];
                af[am][3] = *(const uint32_t*)&As[row0 + 8][k0 + tg * 2 + 8];
            }
#pragma unroll
            for (int an = 0; an < 4; an++) {
                int n0 = nbase + an * 8 + gid;
                bf[an][0] = *(const uint32_t*)&Bs[n0][k0 + tg * 2];
                bf[an][1] = *(const uint32_t*)&Bs[n0][k0 + tg * 2 + 8];
            }
#pragma unroll
            for (int am = 0; am < 4; am++)
#pragma unroll
                for (int an = 0; an < 4; an++)
                    mma_f16(acc[am][an], af[am], bf[an]);
        }
    }

#pragma unroll
    for (int am = 0; am < 4; am++) {
        int row = m0 + mbase + am * 16 + gid;
#pragma unroll
        for (int an = 0; an < 4; an++) {
            int col = nbase + an * 8 + 2 * tg;
            float v0 = acc[am][an][0], v1 = acc[am][an][1];
            float v2 = acc[am][an][2], v3 = acc[am][an][3];
            if (escale) {
                float s0 = escale[col], s1 = escale[col + 1];
                float h0 = eshift[col], h1 = eshift[col + 1];
                v0 = v0 * s0 + h0; v1 = v1 * s1 + h1;
                v2 = v2 * s0 + h0; v3 = v3 * s1 + h1;
                if (do_relu) {
                    v0 = fmaxf(v0, 0.f); v1 = fmaxf(v1, 0.f);
                    v2 = fmaxf(v2, 0.f); v3 = fmaxf(v3, 0.f);
                }
            }
            if (row < M)     *(uint32_t*)&C[(size_t)row * 128 + col]       = f22u(v0, v1);
            if (row + 8 < M) *(uint32_t*)&C[(size_t)(row + 8) * 128 + col] = f22u(v2, v3);
        }
    }
}

// ---------------- logits from fp16 h: als = h @ Wa ----------------
__global__ void k_logits2(const __half* __restrict__ h, int l) {
    int node = blockIdx.x * 4 + (threadIdx.x >> 5);
    int lane = threadIdx.x & 31;
    if (node >= NN) return;
    float4 hv = u2tof4(*(const uint2*)&h[(size_t)node * HD + lane * 4]);
#pragma unroll
    for (int hh = 0; hh < 4; hh++) {
        float4 ws = *(const float4*)&g_wsrc[(l * 4 + hh) * 128 + lane * 4];
        float4 wd = *(const float4*)&g_wdst[(l * 4 + hh) * 128 + lane * 4];
        float ds = hv.x * ws.x + hv.y * ws.y + hv.z * ws.z + hv.w * ws.w;
        float dd = hv.x * wd.x + hv.y * wd.y + hv.z * wd.z + hv.w * wd.w;
#pragma unroll
        for (int off = 16; off > 0; off >>= 1) {
            ds += __shfl_down_sync(0xffffffffu, ds, off);
            dd += __shfl_down_sync(0xffffffffu, dd, off);
        }
        if (lane == 0) { g_als[node * 4 + hh] = ds; g_ald[node * 4 + hh] = dd; }
    }
}

// ------- gather: softmax over edges, aggregate fp16 h[src] per head -> aggh fp16 -------
__global__ void k_gather2(const __half* __restrict__ h, __half* __restrict__ aggh) {
    int node = blockIdx.x * 4 + (threadIdx.x >> 5);
    int lane = threadIdx.x & 31;
    if (node >= NN) return;
    int beg = g_rowptr[node], end = g_rowptr[node + 1];
    float4 ald4 = *(const float4*)&g_ald[node * 4];

    float4 mx = make_float4(-1e30f, -1e30f, -1e30f, -1e30f);
    for (int i = beg + lane; i < end; i += 32) {
        int s = g_csrsrc[i];
        float4 a = *(const float4*)&g_als[s * 4];
        a.x += ald4.x; a.y += ald4.y; a.z += ald4.z; a.w += ald4.w;
        a.x = (a.x >= 0.f) ? a.x : 0.2f * a.x;
        a.y = (a.y >= 0.f) ? a.y : 0.2f * a.y;
        a.z = (a.z >= 0.f) ? a.z : 0.2f * a.z;
        a.w = (a.w >= 0.f) ? a.w : 0.2f * a.w;
        mx.x = fmaxf(mx.x, a.x); mx.y = fmaxf(mx.y, a.y);
        mx.z = fmaxf(mx.z, a.z); mx.w = fmaxf(mx.w, a.w);
    }
#pragma unroll
    for (int off = 16; off > 0; off >>= 1) {
        mx.x = fmaxf(mx.x, __shfl_xor_sync(0xffffffffu, mx.x, off));
        mx.y = fmaxf(mx.y, __shfl_xor_sync(0xffffffffu, mx.y, off));
        mx.z = fmaxf(mx.z, __shfl_xor_sync(0xffffffffu, mx.z, off));
        mx.w = fmaxf(mx.w, __shfl_xor_sync(0xffffffffu, mx.w, off));
    }

    float4 acc0 = make_float4(0, 0, 0, 0), acc1 = acc0, acc2 = acc0, acc3 = acc0;
    float4 sum = make_float4(0, 0, 0, 0);
    for (int i = beg; i < end; i++) {
        int s = g_csrsrc[i];
        float4 a = *(const float4*)&g_als[s * 4];
        a.x += ald4.x; a.y += ald4.y; a.z += ald4.z; a.w += ald4.w;
        a.x = (a.x >= 0.f) ? a.x : 0.2f * a.x;
        a.y = (a.y >= 0.f) ? a.y : 0.2f * a.y;
        a.z = (a.z >= 0.f) ? a.z : 0.2f * a.z;
        a.w = (a.w >= 0.f) ? a.w : 0.2f * a.w;
        float w0 = expf(a.x - mx.x), w1 = expf(a.y - mx.y);
        float w2 = expf(a.z - mx.z), w3 = expf(a.w - mx.w);
        sum.x += w0; sum.y += w1; sum.z += w2; sum.w += w3;
        float4 v = u2tof4(*(const uint2*)&h[(size_t)s * HD + lane * 4]);
        acc0.x += w0 * v.x; acc0.y += w0 * v.y; acc0.z += w0 * v.z; acc0.w += w0 * v.w;
        acc1.x += w1 * v.x; acc1.y += w1 * v.y; acc1.z += w1 * v.z; acc1.w += w1 * v.w;
        acc2.x += w2 * v.x; acc2.y += w2 * v.y; acc2.z += w2 * v.z; acc2.w += w2 * v.w;
        acc3.x += w3 * v.x; acc3.y += w3 * v.y; acc3.z += w3 * v.z; acc3.w += w3 * v.w;
    }
    float i0 = 1.0f / (sum.x + 1e-16f);
    float i1 = 1.0f / (sum.y + 1e-16f);
    float i2 = 1.0f / (sum.z + 1e-16f);
    float i3 = 1.0f / (sum.w + 1e-16f);
    __half* ap = aggh + (size_t)node * 512 + lane * 4;
    *(uint2*)(ap)       = make_uint2(f22u(acc0.x * i0, acc0.y * i0), f22u(acc0.z * i0, acc0.w * i0));
    *(uint2*)(ap + 128) = make_uint2(f22u(acc1.x * i1, acc1.y * i1), f22u(acc1.z * i1, acc1.w * i1));
    *(uint2*)(ap + 256) = make_uint2(f22u(acc2.x * i2, acc2.y * i2), f22u(acc2.z * i2, acc2.w * i2));
    *(uint2*)(ap + 384) = make_uint2(f22u(acc3.x * i3, acc3.y * i3), f22u(acc3.z * i3, acc3.w * i3));
}

// ------- fused edge predictor: LN in smem -> tensor-core GEMM -> reduce ----------
// 256 thr, 128 edges/block. Dynamic smem: wcs(4KB) b1s/gs/os(1.5KB) z1s(34KB) w2s(17KB).
__global__ __launch_bounds__(256) void k_edge_fused(
        const int* __restrict__ src, const int* __restrict__ dst,
        const float* __restrict__ eattr,
        const float* __restrict__ em1b, const float* __restrict__ wc,
        const float* __restrict__ lng, const float* __restrict__ lnb,
        const float* __restrict__ b2, const float* __restrict__ w3,
        const float* __restrict__ b3, float* __restrict__ out) {
    extern __shared__ __align__(16) char smem[];
    float* wcs = (float*)smem;                       // 8*128
    float* b1s = wcs + 1024;                         // 128
    float* gs  = b1s + 128;
    float* os  = gs + 128;
    __half* z1s = (__half*)(smem + 5632);            // 128 x 136
    __half* w2s = z1s + 128 * 136;                   // 64 x 136

    int tid = threadIdx.x;
    ((float4*)wcs)[tid] = ((const float4*)wc)[tid];  // 1024 floats
    if (tid < 128) { b1s[tid] = em1b[tid]; gs[tid] = lng[tid]; os[tid] = lnb[tid]; }
#pragma unroll
    for (int i = 0; i < 4; i++) {                    // w2: 64x128 halves = 1024 uint4
        int idx = tid + i * 256;
        int row = idx >> 4, c8 = (idx & 15) << 3;
        *(uint4*)&w2s[row * 136 + c8] = *(const uint4*)&g_emw2h[(size_t)row * HD + c8];
    }
    __syncthreads();

    int w = tid >> 5, lane = tid & 31;
    int c = lane * 4;
    int e0 = blockIdx.x * 128;

    // Phase A: LN for 128 edges (warp per edge, 16 rounds)
#pragma unroll 4
    for (int it = 0; it < 16; it++) {
        int el = it * 8 + w;
        int e = e0 + el;
        if (e < EE) {
            int s = src[e], d = dst[e];
            const float4* ep = (const float4*)(eattr + (size_t)e * 8);
            float4 ea0 = ep[0], ea1 = ep[1];
            float ea[8] = {ea0.x, ea0.y, ea0.z, ea0.w, ea1.x, ea1.y, ea1.z, ea1.w};
            float4 p4 = u2tof4(*(const uint2*)&g_pqh[(size_t)s * HD + c]);
            float4 q4 = u2tof4(*(const uint2*)&g_pqh[(size_t)NN * HD + (size_t)d * HD + c]);
            float4 b4 = *(const float4*)&b1s[c];
            float4 v;
            v.x = p4.x + q4.x + b4.x;
            v.y = p4.y + q4.y + b4.y;
            v.z = p4.z + q4.z + b4.z;
            v.w = p4.w + q4.w + b4.w;
#pragma unroll
            for (int j = 0; j < 8; j++) {
                float4 w4 = *(const float4*)&wcs[j * 128 + c];
                v.x += ea[j] * w4.x; v.y += ea[j] * w4.y;
                v.z += ea[j] * w4.z; v.w += ea[j] * w4.w;
            }
            float su = v.x + v.y + v.z + v.w;
            float sq = v.x * v.x + v.y * v.y + v.z * v.z + v.w * v.w;
#pragma unroll
            for (int off = 16; off > 0; off >>= 1) {
                su += __shfl_xor_sync(0xffffffffu, su, off);
                sq += __shfl_xor_sync(0xffffffffu, sq, off);
            }
            float mu = su * (1.0f / HD);
            float var = sq * (1.0f / HD) - mu * mu;
            float rs = rsqrtf(var + 1e-5f);
            float4 g4 = *(const float4*)&gs[c];
            float4 o4 = *(const float4*)&os[c];
            float y0 = fmaxf((v.x - mu) * rs * g4.x + o4.x, 0.0f);
            float y1 = fmaxf((v.y - mu) * rs * g4.y + o4.y, 0.0f);
            float y2 = fmaxf((v.z - mu) * rs * g4.z + o4.z, 0.0f);
            float y3 = fmaxf((v.w - mu) * rs * g4.w + o4.w, 0.0f);
            *(uint2*)&z1s[el * 136 + c] = make_uint2(f22u(y0, y1), f22u(y2, y3));
        } else {
            *(uint2*)&z1s[el * 136 + c] = make_uint2(0, 0);
        }
    }
    __syncthreads();

    // Phase B: warp w owns rows w*16..w*16+15; 16x64 tile via m16n8k16
    int gid = lane >> 2, tg = lane & 3;
    int mwarp = w * 16;
    float acc[8][4];
#pragma unroll
    for (int j = 0; j < 8; j++)
#pragma unroll
        for (int q = 0; q < 4; q++) acc[j][q] = 0.0f;

#pragma unroll
    for (int k0 = 0; k0 < 128; k0 += 16) {
        uint32_t af[4], bf[8][2];
        af[0] = *(const uint32_t*)&z1s[(mwarp + gid) * 136 + k0 + tg * 2];
        af[1] = *(const uint32_t*)&z1s[(mwarp + 8 + gid) * 136 + k0 + tg * 2];
        af[2] = *(const uint32_t*)&z1s[(mwarp + gid) * 136 + k0 + tg * 2 + 8];
        af[3] = *(const uint32_t*)&z1s[(mwarp + 8 + gid) * 136 + k0 + tg * 2 + 8];
#pragma unroll
        for (int an = 0; an < 8; an++) {
            int n0 = an * 8 + gid;
            bf[an][0] = *(const uint32_t*)&w2s[n0 * 136 + k0 + tg * 2];
            bf[an][1] = *(const uint32_t*)&w2s[n0 * 136 + k0 + tg * 2 + 8];
        }
#pragma unroll
        for (int an = 0; an < 8; an++)
            mma_f16(acc[an], af, bf[an]);
    }

    float b3v = b3[0];
    float r0sum = 0.0f, r1sum = 0.0f;
#pragma unroll
    for (int an = 0; an < 8; an++) {
        int cA = an * 8 + 2 * tg;
        float b2a = b2[cA], b2b = b2[cA + 1];
        float w3a = w3[cA], w3b = w3[cA + 1];
        r0sum += fmaxf(acc[an][0] + b2a, 0.0f) * w3a
               + fmaxf(acc[an][1] + b2b, 0.0f) * w3b;
        r1sum += fmaxf(acc[an][2] + b2a, 0.0f) * w3a
               + fmaxf(acc[an][3] + b2b, 0.0f) * w3b;
    }
    r0sum += __shfl_down_sync(0xffffffffu, r0sum, 2, 4);
    r0sum += __shfl_down_sync(0xffffffffu, r0sum, 1, 4);
    r1sum += __shfl_down_sync(0xffffffffu, r1sum, 2, 4);
    r1sum += __shfl_down_sync(0xffffffffu, r1sum, 1, 4);
    if (tg == 0) {
        int row = e0 + mwarp + gid;
        if (row < EE)     out[row]     = r0sum + b3v;
        if (row + 8 < EE) out[row + 8] = r1sum + b3v;
    }
}

// ---------------- launch ----------------
extern "C" void kernel_launch(void* const* d_in, const int* in_sizes, int n_in,
                              void* d_out, int out_size) {
    const float* x       = (const float*)d_in[0];
    const int*   ei      = (const int*)d_in[1];
    const float* eattr   = (const float*)d_in[2];
    const int*   shock   = (const int*)d_in[3];
    const float* enc_w   = (const float*)d_in[4];
    const float* enc_b   = (const float*)d_in[5];
    const float* enc_lng = (const float*)d_in[6];
    const float* enc_lnb = (const float*)d_in[7];
    const float* gat_w   = (const float*)d_in[8];
    const float* att_src = (const float*)d_in[9];
    const float* att_dst = (const float*)d_in[10];
    const float* gat_bias= (const float*)d_in[11];
    const float* bn_g    = (const float*)d_in[12];
    const float* bn_b    = (const float*)d_in[13];
    const float* bn_m    = (const float*)d_in[14];
    const float* bn_v    = (const float*)d_in[15];
    const float* em1_w   = (const float*)d_in[16];
    const float* em1_b   = (const float*)d_in[17];
    const float* em_lng  = (const float*)d_in[18];
    const float* em_lnb  = (const float*)d_in[19];
    const float* em2_w   = (const float*)d_in[20];
    const float* em2_b   = (const float*)d_in[21];
    const float* em3_w   = (const float*)d_in[22];
    const float* em3_b   = (const float*)d_in[23];
    const int* src = ei;
    const int* dst = ei + EE;
    float* out = (float*)d_out;

    float *pbnsc, *pbnsh;
    __half *phh, *phh2, *paggh, *ppqh, *pwh, *pempq;
    cudaGetSymbolAddress((void**)&phh,   g_hh);
    cudaGetSymbolAddress((void**)&phh2,  g_hh2);
    cudaGetSymbolAddress((void**)&paggh, g_aggh);
    cudaGetSymbolAddress((void**)&ppqh,  g_pqh);
    cudaGetSymbolAddress((void**)&pwh,   g_wpermh);
    cudaGetSymbolAddress((void**)&pempq, g_empq);
    cudaGetSymbolAddress((void**)&pbnsc, g_bnscale);
    cudaGetSymbolAddress((void**)&pbnsh, g_bnshift);

    static int smem_set = 0;
    const int edge_smem = 5632 + 128 * 136 * 2 + 64 * 136 * 2;  // 57856 B
    if (!smem_set) {
        cudaFuncSetAttribute(k_edge_fused, cudaFuncAttributeMaxDynamicSharedMemorySize, edge_smem);
        smem_set = 1;
    }

    // graph prep (encoder at launch #4 for the ncu window)
    k_zero_misc<<<(NN + 255) / 256, 256>>>();
    k_downcount<<<(E2 + 255) / 256, 256>>>(src, dst, shock);
    int nb = (NN + 1023) / 1024;
    k_scan1<<<nb, 1024>>>();
    k_encoder2<<<(NN + 63) / 64, 256>>>(x, shock, enc_w, enc_b, enc_lng, enc_lnb, phh);
    k_scan2<<<1, 64>>>(nb);
    k_scan3<<<(NN + 255) / 256, 256>>>();
    k_scatter<<<(E2 + 255) / 256, 256>>>(src, dst);

    // weight prep
    k_watt<<<dim3(3, 4), 128>>>(gat_w, att_src, att_dst);
    k_permw_h<<<dim3(3, 512), 128>>>(gat_w);
    k_prep_em<<<128, 128>>>(em1_w, em2_w);
    k_bnprep<<<3, 128>>>(gat_bias, bn_g, bn_b, bn_m, bn_v);

    // 3 GAT layers
    __half* hin = phh;
    __half* hout = phh2;
    int gx = (NN + 127) / 128;
    for (int l = 0; l < 3; l++) {
        k_logits2<<<(NN + 3) / 4, 128>>>(hin, l);
        k_gather2<<<(NN + 3) / 4, 128>>>(hin, paggh);
        gemm_f16<<<dim3(gx, 1), 256>>>(paggh, pwh + (size_t)l * 128 * 512, hout, NN, 512,
                                       pbnsc + l * 128, pbnsh + l * 128, (l < 2) ? 1 : 0, 0, 0);
        __half* tmp = hin; hin = hout; hout = tmp;
    }

    // p and q in one launch: grid.y selects weight half and output half
    gemm_f16<<<dim3(gx, 2), 256>>>(hin, pempq, ppqh, NN, 128, nullptr, nullptr, 0,
                                   128 * 128, (long)NN * HD);

    // fused edge predictor
    k_edge_fused<<<(EE + 127) / 128, 256, edge_smem>>>(
        src, dst, eattr, em1_b, em1_w + 256 * HD, em_lng, em_lnb,
        em2_b, em3_w, em3_b, out);
}

// round 13
// speedup vs baseline: 1.5609x; 1.5609x over previous
#include <cuda_runtime.h>
#include <cuda_bf16.h>
#include <cuda_fp16.h>
#include <math.h>
#include <stdint.h>

#define NN 50000
#define EE 200000
#define E2 (EE + NN)
#define HD 128

// ---------------- scratch (static device globals; no allocation) ----------------
__device__ int   g_down[NN];
__device__ __align__(16) float g_h[NN * HD];
__device__ __align__(16) float g_h2[NN * HD];
__device__ __align__(16) __half g_aggh[(size_t)NN * 512];
__device__ __align__(16) float g_als[NN * 4];
__device__ __align__(16) float g_ald[NN * 4];
__device__ int   g_cnt[NN];
__device__ int   g_rowtmp[NN];
__device__ int   g_bsum[64];
__device__ int   g_rowptr[NN + 1];
__device__ int   g_cursor[NN];
__device__ int   g_csrsrc[E2];
__device__ __align__(16) __half g_pqh[2 * (size_t)NN * HD];   // p then q
__device__ __align__(16) __half g_z1[(size_t)(EE + 128) * HD];
__device__ __align__(16) float g_wsrc[3 * 4 * 128];
__device__ __align__(16) float g_wdst[3 * 4 * 128];
__device__ __align__(16) __half g_wpermh[3 * 128 * 512];  // [l][cout][kk]
__device__ __align__(16) __half g_empq[2 * 128 * 128];    // [n][k] p-half then q-half
__device__ __align__(16) __half g_emw2h[64 * 128];        // [n][k]
__device__ __align__(16) float g_bnscale[3 * 128];
__device__ __align__(16) float g_bnshift[3 * 128];

__device__ __forceinline__ uint32_t f22u(float a, float b) {
    __half2 h = __floats2half2_rn(a, b);
    return *(uint32_t*)&h;
}
__device__ __forceinline__ float4 u2tof4(uint2 u) {
    float2 a = __half22float2(*(__half2*)&u.x);
    float2 b = __half22float2(*(__half2*)&u.y);
    return make_float4(a.x, a.y, b.x, b.y);
}

// ---------------- small helpers ----------------
__global__ void k_zero_misc() {
    int i = blockIdx.x * blockDim.x + threadIdx.x;
    if (i < NN) { g_down[i] = 0; g_cnt[i] = 0; }
}

__global__ void k_downcount(const int* __restrict__ src, const int* __restrict__ dst,
                            const int* __restrict__ shock) {
    int e = blockIdx.x * blockDim.x + threadIdx.x;
    if (e >= E2) return;
    if (e < EE) {
        int s = src[e], d = dst[e];
        if (shock[s] != 0) g_down[d] = 1;
        atomicAdd(&g_cnt[d], 1);
    } else {
        atomicAdd(&g_cnt[e - EE], 1);
    }
}

__global__ void k_scan1() {
    __shared__ int sh[1024];
    int tid = threadIdx.x;
    int i = blockIdx.x * 1024 + tid;
    int v = (i < NN) ? g_cnt[i] : 0;
    sh[tid] = v;
    __syncthreads();
    for (int off = 1; off < 1024; off <<= 1) {
        int t = (tid >= off) ? sh[tid - off] : 0;
        __syncthreads();
        sh[tid] += t;
        __syncthreads();
    }
    int incl = sh[tid];
    if (i < NN) g_rowtmp[i] = incl - v;
    if (tid == 1023) g_bsum[blockIdx.x] = incl;
}

// parallel exclusive scan over <=64 block sums
__global__ void k_scan2(int nb) {
    __shared__ int sh[64];
    int t = threadIdx.x;
    int v = (t < nb) ? g_bsum[t] : 0;
    sh[t] = v;
    __syncthreads();
    for (int off = 1; off < 64; off <<= 1) {
        int u = (t >= off) ? sh[t - off] : 0;
        __syncthreads();
        sh[t] += u;
        __syncthreads();
    }
    if (t < nb) g_bsum[t] = sh[t] - v;
}

__global__ void k_scan3() {
    int i = blockIdx.x * blockDim.x + threadIdx.x;
    if (i >= NN) return;
    int r = g_rowtmp[i] + g_bsum[i >> 10];
    g_rowptr[i] = r;
    g_cursor[i] = r;
    if (i == NN - 1) g_rowptr[NN] = E2;
}

__global__ void k_scatter(const int* __restrict__ src, const int* __restrict__ dst) {
    int e = blockIdx.x * blockDim.x + threadIdx.x;
    if (e >= E2) return;
    int s, d;
    if (e < EE) { s = src[e]; d = dst[e]; } else { s = e - EE; d = e - EE; }
    int pos = atomicAdd(&g_cursor[d], 1);
    g_csrsrc[pos] = s;
}

// ---------------- node encoder: 64 nodes/block, W in smem, warp-per-node ----
__global__ __launch_bounds__(256) void k_encoder2(
        const float* __restrict__ x, const int* __restrict__ shock,
        const float* __restrict__ W, const float* __restrict__ b,
        const float* __restrict__ lng, const float* __restrict__ lnb,
        float* __restrict__ hout) {
    __shared__ __align__(16) float Ws[18][128];
    __shared__ __align__(16) float bs[128], gs[128], os[128];
    int tid = threadIdx.x;
#pragma unroll
    for (int i = 0; i < 3; i++) {
        int idx = tid + i * 256;
        if (idx < 576) ((float4*)Ws)[idx] = ((const float4*)W)[idx];
    }
    if (tid < 128) { bs[tid] = b[tid]; gs[tid] = lng[tid]; os[tid] = lnb[tid]; }
    __syncthreads();

    int w = tid >> 5, lane = tid & 31;
#pragma unroll
    for (int it = 0; it < 8; it++) {
        int n = blockIdx.x * 64 + it * 8 + w;
        if (n >= NN) continue;
        const float4* xr = (const float4*)(x + n * 16);
        float4 x0 = xr[0], x1 = xr[1], x2 = xr[2], x3 = xr[3];
        float sh_ = (float)shock[n];
        float dn_ = (float)g_down[n];
        float xa[16] = {x0.x, x0.y, x0.z, x0.w, x1.x, x1.y, x1.z, x1.w,
                        x2.x, x2.y, x2.z, x2.w, x3.x, x3.y, x3.z, x3.w};
        int c = lane * 4;
        float4 v = *(const float4*)&bs[c];
#pragma unroll
        for (int j = 0; j < 16; j++) {
            float4 w4 = *(const float4*)&Ws[j][c];
            v.x += xa[j] * w4.x; v.y += xa[j] * w4.y;
            v.z += xa[j] * w4.z; v.w += xa[j] * w4.w;
        }
        {
            float4 w4 = *(const float4*)&Ws[16][c];
            v.x += sh_ * w4.x; v.y += sh_ * w4.y; v.z += sh_ * w4.z; v.w += sh_ * w4.w;
            float4 w5 = *(const float4*)&Ws[17][c];
            v.x += dn_ * w5.x; v.y += dn_ * w5.y; v.z += dn_ * w5.z; v.w += dn_ * w5.w;
        }
        float su = v.x + v.y + v.z + v.w;
        float sq = v.x * v.x + v.y * v.y + v.z * v.z + v.w * v.w;
#pragma unroll
        for (int off = 16; off > 0; off >>= 1) {
            su += __shfl_xor_sync(0xffffffffu, su, off);
            sq += __shfl_xor_sync(0xffffffffu, sq, off);
        }
        float mu = su * (1.0f / HD);
        float var = sq * (1.0f / HD) - mu * mu;
        float rs = rsqrtf(var + 1e-5f);
        float4 g4 = *(const float4*)&gs[c];
        float4 o4 = *(const float4*)&os[c];
        float4 y;
        y.x = fmaxf((v.x - mu) * rs * g4.x + o4.x, 0.0f);
        y.y = fmaxf((v.y - mu) * rs * g4.y + o4.y, 0.0f);
        y.z = fmaxf((v.z - mu) * rs * g4.z + o4.z, 0.0f);
        y.w = fmaxf((v.w - mu) * rs * g4.w + o4.w, 0.0f);
        *(float4*)&hout[(size_t)n * HD + c] = y;
    }
}

// ---------------- weight prep ----------------
__global__ void k_watt(const float* __restrict__ gw,
                       const float* __restrict__ as_, const float* __restrict__ ad_) {
    int l = blockIdx.x, h = blockIdx.y;
    int k = threadIdx.x;
    __shared__ float s_as[128], s_ad[128];
    s_as[k] = as_[(l * 4 + h) * 128 + k];
    s_ad[k] = ad_[(l * 4 + h) * 128 + k];
    __syncthreads();
    const float* wrow = gw + ((size_t)l * 128 + k) * 512 + h * 128;
    float ss = 0.0f, sd = 0.0f;
#pragma unroll 8
    for (int cc = 0; cc < 128; cc++) {
        float w = wrow[cc];
        ss += w * s_as[cc];
        sd += w * s_ad[cc];
    }
    g_wsrc[(l * 4 + h) * 128 + k] = ss;
    g_wdst[(l * 4 + h) * 128 + k] = sd;
}

__global__ void k_permw_h(const float* __restrict__ gw) {
    int l = blockIdx.x;
    int kk = blockIdx.y;
    int cout = threadIdx.x;
    int k_in = kk & 127, hd = kk >> 7;
    float v = 0.25f * gw[((size_t)l * 128 + k_in) * 512 + (hd << 7) + cout];
    g_wpermh[((size_t)l * 128 + cout) * 512 + kk] = __float2half(v);
}

__global__ void k_prep_em(const float* __restrict__ em1w, const float* __restrict__ em2w) {
    int n = blockIdx.x;
    int k = threadIdx.x;
    g_empq[n * 128 + k]             = __float2half(em1w[(size_t)k * 128 + n]);
    g_empq[128 * 128 + n * 128 + k] = __float2half(em1w[(size_t)(128 + k) * 128 + n]);
    if (n < 64) g_emw2h[n * 128 + k] = __float2half(em2w[(size_t)k * 64 + n]);
}

__global__ void k_bnprep(const float* __restrict__ bias, const float* __restrict__ bng,
                         const float* __restrict__ bnb, const float* __restrict__ bnm,
                         const float* __restrict__ bnv) {
    int l = blockIdx.x, c = threadIdx.x;
    int i = l * 128 + c;
    float sc = bng[i] * rsqrtf(bnv[i] + 1e-5f);
    g_bnscale[i] = sc;
    g_bnshift[i] = (bias[i] - bnm[i]) * sc + bnb[i];
}

// ---------------- fp16 tensor-core GEMM: C[M,128] = A[M,K] @ B^T ----------------
__device__ __forceinline__ void mma_f16(float* d, const uint32_t* a, const uint32_t* b) {
    asm volatile(
        "mma.sync.aligned.m16n8k16.row.col.f32.f16.f16.f32 "
        "{%0,%1,%2,%3}, {%4,%5,%6,%7}, {%8,%9}, {%0,%1,%2,%3};\n"
        : "+f"(d[0]), "+f"(d[1]), "+f"(d[2]), "+f"(d[3])
        : "r"(a[0]), "r"(a[1]), "r"(a[2]), "r"(a[3]), "r"(b[0]), "r"(b[1]));
}

template <int AH, int OH>
__global__ __launch_bounds__(256) void gemm_f16(const void* __restrict__ Av,
                                                const __half* __restrict__ B0,
                                                void* __restrict__ Cv,
                                                int M, int K,
                                                const float* __restrict__ escale,
                                                const float* __restrict__ eshift,
                                                int do_relu, long bStride, long cStride) {
    __shared__ __align__(16) __half As[128][40];
    __shared__ __align__(16) __half Bs[128][40];
    const __half* B = B0 + blockIdx.y * bStride;
    int tid = threadIdx.x;
    int m0 = blockIdx.x * 128;
    int lane = tid & 31, wid = tid >> 5;
    int mbase = (wid & 1) * 64;
    int nbase = (wid >> 1) * 32;
    int gid = lane >> 2, tg = lane & 3;

    float acc[4][4][4];
#pragma unroll
    for (int i = 0; i < 4; i++)
#pragma unroll
        for (int j = 0; j < 4; j++)
#pragma unroll
            for (int q = 0; q < 4; q++) acc[i][j][q] = 0.0f;

    for (int kc = 0; kc < K; kc += 32) {
        __syncthreads();
        if (AH) {
            const __half* A = (const __half*)Av;
#pragma unroll
            for (int i = 0; i < 2; i++) {
                int l4 = tid + i * 256;
                int row = l4 >> 2, c8 = (l4 & 3) << 3;
                uint4 v = make_uint4(0, 0, 0, 0);
                int gr = m0 + row;
                if (gr < M) v = *(const uint4*)&A[(size_t)gr * K + kc + c8];
                *(uint4*)&As[row][c8] = v;
            }
        } else {
            const float* A = (const float*)Av;
#pragma unroll
            for (int i = 0; i < 4; i++) {
                int l4 = tid + i * 256;
                int row = l4 >> 3, c4 = (l4 & 7) << 2;
                float4 v = make_float4(0.f, 0.f, 0.f, 0.f);
                int gr = m0 + row;
                if (gr < M) v = *(const float4*)&A[(size_t)gr * K + kc + c4];
                *(__half2*)&As[row][c4]     = __floats2half2_rn(v.x, v.y);
                *(__half2*)&As[row][c4 + 2] = __floats2half2_rn(v.z, v.w);
            }
        }
#pragma unroll
        for (int i = 0; i < 2; i++) {
            int l = tid + i * 256;
            int n = l >> 2, k8 = (l & 3) << 3;
            uint4 v = *(const uint4*)&B[(size_t)n * K + kc + k8];
            *(uint4*)&Bs[n][k8] = v;
        }
        __syncthreads();

#pragma unroll
        for (int k0 = 0; k0 < 32; k0 += 16) {
            uint32_t af[4][4], bf[4][2];
#pragma unroll
            for (int am = 0; am < 4; am++) {
                int row0 = mbase + am * 16 + gid;
                af[am][0] = *(const uint32_t*)&As[row0][k0 + tg * 2];
                af[am][1] = *(const uint32_t*)&As[row0 + 8][k0 + tg * 2];
                af[am][2] = *(const uint32_t*)&As[row0][k0 + tg * 2 + 8];
                af[am][3] = *(const uint32_t*)&As[row0 + 8][k0 + tg * 2 + 8];
            }
#pragma unroll
            for (int an = 0; an < 4; an++) {
                int n0 = nbase + an * 8 + gid;
                bf[an][0] = *(const uint32_t*)&Bs[n0][k0 + tg * 2];
                bf[an][1] = *(const uint32_t*)&Bs[n0][k0 + tg * 2 + 8];
            }
#pragma unroll
            for (int am = 0; am < 4; am++)
#pragma unroll
                for (int an = 0; an < 4; an++)
                    mma_f16(acc[am][an], af[am], bf[an]);
        }
    }

#pragma unroll
    for (int am = 0; am < 4; am++) {
        int row = m0 + mbase + am * 16 + gid;
#pragma unroll
        for (int an = 0; an < 4; an++) {
            int col = nbase + an * 8 + 2 * tg;
            float v0 = acc[am][an][0], v1 = acc[am][an][1];
            float v2 = acc[am][an][2], v3 = acc[am][an][3];
            if (escale) {
                float s0 = escale[col], s1 = escale[col + 1];
                float h0 = eshift[col], h1 = eshift[col + 1];
                v0 = v0 * s0 + h0; v1 = v1 * s1 + h1;
                v2 = v2 * s0 + h0; v3 = v3 * s1 + h1;
                if (do_relu) {
                    v0 = fmaxf(v0, 0.f); v1 = fmaxf(v1, 0.f);
                    v2 = fmaxf(v2, 0.f); v3 = fmaxf(v3, 0.f);
                }
            }
            if (OH) {
                __half* C = (__half*)Cv + blockIdx.y * cStride;
                if (row < M)     *(uint32_t*)&C[(size_t)row * 128 + col]       = f22u(v0, v1);
                if (row + 8 < M) *(uint32_t*)&C[(size_t)(row + 8) * 128 + col] = f22u(v2, v3);
            } else {
                float* C = (float*)Cv;
                if (row < M)     *(float2*)&C[(size_t)row * 128 + col]       = make_float2(v0, v1);
                if (row + 8 < M) *(float2*)&C[(size_t)(row + 8) * 128 + col] = make_float2(v2, v3);
            }
        }
    }
}

// ---------------- logits from h directly: als = h @ Wa ----------------
__global__ void k_logits2(const float* __restrict__ h, int l) {
    int node = blockIdx.x * 4 + (threadIdx.x >> 5);
    int lane = threadIdx.x & 31;
    if (node >= NN) return;
    float4 hv = *(const float4*)&h[(size_t)node * HD + lane * 4];
#pragma unroll
    for (int hh = 0; hh < 4; hh++) {
        float4 ws = *(const float4*)&g_wsrc[(l * 4 + hh) * 128 + lane * 4];
        float4 wd = *(const float4*)&g_wdst[(l * 4 + hh) * 128 + lane * 4];
        float ds = hv.x * ws.x + hv.y * ws.y + hv.z * ws.z + hv.w * ws.w;
        float dd = hv.x * wd.x + hv.y * wd.y + hv.z * wd.z + hv.w * wd.w;
#pragma unroll
        for (int off = 16; off > 0; off >>= 1) {
            ds += __shfl_down_sync(0xffffffffu, ds, off);
            dd += __shfl_down_sync(0xffffffffu, dd, off);
        }
        if (lane == 0) { g_als[node * 4 + hh] = ds; g_ald[node * 4 + hh] = dd; }
    }
}

// ------- gather: softmax + aggregate h[src] per head -> aggh[N,512] fp16 -------
// Fast path (deg<=32): logits/exp computed lane-parallel once, weights shuffled.
__global__ void k_gather2(const float* __restrict__ h, __half* __restrict__ aggh) {
    int node = blockIdx.x * 4 + (threadIdx.x >> 5);
    int lane = threadIdx.x & 31;
    if (node >= NN) return;
    int beg = g_rowptr[node], end = g_rowptr[node + 1];
    int deg = end - beg;
    float4 ald4 = *(const float4*)&g_ald[node * 4];

    float4 acc0 = make_float4(0, 0, 0, 0), acc1 = acc0, acc2 = acc0, acc3 = acc0;
    float4 sum = make_float4(0, 0, 0, 0);

    if (deg <= 32) {
        int s = 0;
        float4 a = make_float4(-1e30f, -1e30f, -1e30f, -1e30f);
        if (lane < deg) {
            s = g_csrsrc[beg + lane];
            a = *(const float4*)&g_als[s * 4];
            a.x += ald4.x; a.y += ald4.y; a.z += ald4.z; a.w += ald4.w;
            a.x = (a.x >= 0.f) ? a.x : 0.2f * a.x;
            a.y = (a.y >= 0.f) ? a.y : 0.2f * a.y;
            a.z = (a.z >= 0.f) ? a.z : 0.2f * a.z;
            a.w = (a.w >= 0.f) ? a.w : 0.2f * a.w;
        }
        float4 mx = a;
#pragma unroll
        for (int off = 16; off > 0; off >>= 1) {
            mx.x = fmaxf(mx.x, __shfl_xor_sync(0xffffffffu, mx.x, off));
            mx.y = fmaxf(mx.y, __shfl_xor_sync(0xffffffffu, mx.y, off));
            mx.z = fmaxf(mx.z, __shfl_xor_sync(0xffffffffu, mx.z, off));
            mx.w = fmaxf(mx.w, __shfl_xor_sync(0xffffffffu, mx.w, off));
        }
        float4 w = make_float4(0, 0, 0, 0);
        if (lane < deg) {
            w.x = expf(a.x - mx.x); w.y = expf(a.y - mx.y);
            w.z = expf(a.z - mx.z); w.w = expf(a.w - mx.w);
        }
        sum = w;
#pragma unroll
        for (int off = 16; off > 0; off >>= 1) {
            sum.x += __shfl_xor_sync(0xffffffffu, sum.x, off);
            sum.y += __shfl_xor_sync(0xffffffffu, sum.y, off);
            sum.z += __shfl_xor_sync(0xffffffffu, sum.z, off);
            sum.w += __shfl_xor_sync(0xffffffffu, sum.w, off);
        }
        for (int j = 0; j < deg; j++) {
            int sj  = __shfl_sync(0xffffffffu, s, j);
            float w0 = __shfl_sync(0xffffffffu, w.x, j);
            float w1 = __shfl_sync(0xffffffffu, w.y, j);
            float w2 = __shfl_sync(0xffffffffu, w.z, j);
            float w3 = __shfl_sync(0xffffffffu, w.w, j);
            float4 v = *(const float4*)&h[(size_t)sj * HD + lane * 4];
            acc0.x += w0 * v.x; acc0.y += w0 * v.y; acc0.z += w0 * v.z; acc0.w += w0 * v.w;
            acc1.x += w1 * v.x; acc1.y += w1 * v.y; acc1.z += w1 * v.z; acc1.w += w1 * v.w;
            acc2.x += w2 * v.x; acc2.y += w2 * v.y; acc2.z += w2 * v.z; acc2.w += w2 * v.w;
            acc3.x += w3 * v.x; acc3.y += w3 * v.y; acc3.z += w3 * v.z; acc3.w += w3 * v.w;
        }
    } else {
        // fallback: two-pass exact (degrees > 32)
        float4 mx = make_float4(-1e30f, -1e30f, -1e30f, -1e30f);
        for (int i = beg + lane; i < end; i += 32) {
            int s = g_csrsrc[i];
            float4 a = *(const float4*)&g_als[s * 4];
            a.x += ald4.x; a.y += ald4.y; a.z += ald4.z; a.w += ald4.w;
            a.x = (a.x >= 0.f) ? a.x : 0.2f * a.x;
            a.y = (a.y >= 0.f) ? a.y : 0.2f * a.y;
            a.z = (a.z >= 0.f) ? a.z : 0.2f * a.z;
            a.w = (a.w >= 0.f) ? a.w : 0.2f * a.w;
            mx.x = fmaxf(mx.x, a.x); mx.y = fmaxf(mx.y, a.y);
            mx.z = fmaxf(mx.z, a.z); mx.w = fmaxf(mx.w, a.w);
        }
#pragma unroll
        for (int off = 16; off > 0; off >>= 1) {
            mx.x = fmaxf(mx.x, __shfl_xor_sync(0xffffffffu, mx.x, off));
            mx.y = fmaxf(mx.y, __shfl_xor_sync(0xffffffffu, mx.y, off));
            mx.z = fmaxf(mx.z, __shfl_xor_sync(0xffffffffu, mx.z, off));
            mx.w = fmaxf(mx.w, __shfl_xor_sync(0xffffffffu, mx.w, off));
        }
        for (int i = beg; i < end; i++) {
            int s = g_csrsrc[i];
            float4 a = *(const float4*)&g_als[s * 4];
            a.x += ald4.x; a.y += ald4.y; a.z += ald4.z; a.w += ald4.w;
            a.x = (a.x >= 0.f) ? a.x : 0.2f * a.x;
            a.y = (a.y >= 0.f) ? a.y : 0.2f * a.y;
            a.z = (a.z >= 0.f) ? a.z : 0.2f * a.z;
            a.w = (a.w >= 0.f) ? a.w : 0.2f * a.w;
            float w0 = expf(a.x - mx.x), w1 = expf(a.y - mx.y);
            float w2 = expf(a.z - mx.z), w3 = expf(a.w - mx.w);
            sum.x += w0; sum.y += w1; sum.z += w2; sum.w += w3;
            float4 v = *(const float4*)&h[(size_t)s * HD + lane * 4];
            acc0.x += w0 * v.x; acc0.y += w0 * v.y; acc0.z += w0 * v.z; acc0.w += w0 * v.w;
            acc1.x += w1 * v.x; acc1.y += w1 * v.y; acc1.z += w1 * v.z; acc1.w += w1 * v.w;
            acc2.x += w2 * v.x; acc2.y += w2 * v.y; acc2.z += w2 * v.z; acc2.w += w2 * v.w;
            acc3.x += w3 * v.x; acc3.y += w3 * v.y; acc3.z += w3 * v.z; acc3.w += w3 * v.w;
        }
    }

    float i0 = 1.0f / (sum.x + 1e-16f);
    float i1 = 1.0f / (sum.y + 1e-16f);
    float i2 = 1.0f / (sum.z + 1e-16f);
    float i3 = 1.0f / (sum.w + 1e-16f);
    __half* ap = aggh + (size_t)node * 512 + lane * 4;
    *(uint2*)(ap)       = make_uint2(f22u(acc0.x * i0, acc0.y * i0), f22u(acc0.z * i0, acc0.w * i0));
    *(uint2*)(ap + 128) = make_uint2(f22u(acc1.x * i1, acc1.y * i1), f22u(acc1.z * i1, acc1.w * i1));
    *(uint2*)(ap + 256) = make_uint2(f22u(acc2.x * i2, acc2.y * i2), f22u(acc2.z * i2, acc2.w * i2));
    *(uint2*)(ap + 384) = make_uint2(f22u(acc3.x * i3, acc3.y * i3), f22u(acc3.z * i3, acc3.w * i3));
}

// ------- edge LN: warp per edge, z1 = relu(LN(p[s]+q[d]+ea@Wc+b1)) -> fp16 --------
__global__ __launch_bounds__(256) void k_edge_ln(
        const int* __restrict__ src, const int* __restrict__ dst,
        const float* __restrict__ eattr,
        const float* __restrict__ em1b, const float* __restrict__ wc,
        const float* __restrict__ lng, const float* __restrict__ lnb) {
    __shared__ __align__(16) float wcs[8][128];
    __shared__ __align__(16) float b1s[128], gs[128], os[128];
    int tid = threadIdx.x;
    ((float4*)wcs)[tid] = ((const float4*)wc)[tid];
    if (tid < 128) { b1s[tid] = em1b[tid]; gs[tid] = lng[tid]; os[tid] = lnb[tid]; }
    __syncthreads();

    int w = tid >> 5, lane = tid & 31;
    int e = blockIdx.x * 8 + w;
    int s = src[e], d = dst[e];
    const float4* ep = (const float4*)(eattr + (size_t)e * 8);
    float4 ea0 = ep[0], ea1 = ep[1];
    float ea[8] = {ea0.x, ea0.y, ea0.z, ea0.w, ea1.x, ea1.y, ea1.z, ea1.w};
    int c = lane * 4;

    float4 p4 = u2tof4(*(const uint2*)&g_pqh[(size_t)s * HD + c]);
    float4 q4 = u2tof4(*(const uint2*)&g_pqh[(size_t)NN * HD + (size_t)d * HD + c]);
    float4 b4 = *(const float4*)&b1s[c];
    float4 v;
    v.x = p4.x + q4.x + b4.x;
    v.y = p4.y + q4.y + b4.y;
    v.z = p4.z + q4.z + b4.z;
    v.w = p4.w + q4.w + b4.w;
#pragma unroll
    for (int j = 0; j < 8; j++) {
        float4 w4 = *(const float4*)&wcs[j][c];
        v.x += ea[j] * w4.x; v.y += ea[j] * w4.y;
        v.z += ea[j] * w4.z; v.w += ea[j] * w4.w;
    }
    float su = v.x + v.y + v.z + v.w;
    float sq = v.x * v.x + v.y * v.y + v.z * v.z + v.w * v.w;
#pragma unroll
    for (int off = 16; off > 0; off >>= 1) {
        su += __shfl_xor_sync(0xffffffffu, su, off);
        sq += __shfl_xor_sync(0xffffffffu, sq, off);
    }
    float mu = su * (1.0f / HD);
    float var = sq * (1.0f / HD) - mu * mu;
    float rs = rsqrtf(var + 1e-5f);
    float4 g4 = *(const float4*)&gs[c];
    float4 o4 = *(const float4*)&os[c];
    float y0 = fmaxf((v.x - mu) * rs * g4.x + o4.x, 0.0f);
    float y1 = fmaxf((v.y - mu) * rs * g4.y + o4.y, 0.0f);
    float y2 = fmaxf((v.z - mu) * rs * g4.z + o4.z, 0.0f);
    float y3 = fmaxf((v.w - mu) * rs * g4.w + o4.w, 0.0f);
    *(uint2*)&g_z1[(size_t)e * HD + c] = make_uint2(f22u(y0, y1), f22u(y2, y3));
}

// ------- edge GEMM: out[e] = relu(z1[e]@W2 + b2) . w3 + b3, tensor-core ---------
__global__ __launch_bounds__(128) void k_edge_gemm(
        const float* __restrict__ b2, const float* __restrict__ w3,
        const float* __restrict__ b3, float* __restrict__ out) {
    __shared__ __align__(16) __half z1s[128][136];
    __shared__ __align__(16) __half w2s[64][136];
    int tid = threadIdx.x;
    int r0 = blockIdx.x * 128;
#pragma unroll
    for (int i = 0; i < 16; i++) {
        int idx = tid + i * 128;
        int row = idx >> 4, c8 = (idx & 15) << 3;
        *(uint4*)&z1s[row][c8] = *(const uint4*)&g_z1[(size_t)(r0 + row) * HD + c8];
    }
#pragma unroll
    for (int i = 0; i < 8; i++) {
        int idx = tid + i * 128;
        int row = idx >> 4, c8 = (idx & 15) << 3;
        *(uint4*)&w2s[row][c8] = *(const uint4*)&g_emw2h[(size_t)row * HD + c8];
    }
    __syncthreads();

    int w = tid >> 5, lane = tid & 31;
    int gid = lane >> 2, tg = lane & 3;
    int mwarp = w * 32;

    float acc[2][8][4];
#pragma unroll
    for (int i = 0; i < 2; i++)
#pragma unroll
        for (int j = 0; j < 8; j++)
#pragma unroll
            for (int q = 0; q < 4; q++) acc[i][j][q] = 0.0f;

#pragma unroll
    for (int k0 = 0; k0 < 128; k0 += 16) {
        uint32_t af[2][4], bf[8][2];
#pragma unroll
        for (int am = 0; am < 2; am++) {
            int row0 = mwarp + am * 16 + gid;
            af[am][0] = *(const uint32_t*)&z1s[row0][k0 + tg * 2];
            af[am][1] = *(const uint32_t*)&z1s[row0 + 8][k0 + tg * 2];
            af[am][2] = *(const uint32_t*)&z1s[row0][k0 + tg * 2 + 8];
            af[am][3] = *(const uint32_t*)&z1s[row0 + 8][k0 + tg * 2 + 8];
        }
#pragma unroll
        for (int an = 0; an < 8; an++) {
            int n0 = an * 8 + gid;
            bf[an][0] = *(const uint32_t*)&w2s[n0][k0 + tg * 2];
            bf[an][1] = *(const uint32_t*)&w2s[n0][k0 + tg * 2 + 8];
        }
#pragma unroll
        for (int am = 0; am < 2; am++)
#pragma unroll
            for (int an = 0; an < 8; an++)
                mma_f16(acc[am][an], af[am], bf[an]);
    }

    float b3v = b3[0];
#pragma unroll
    for (int am = 0; am < 2; am++) {
        float r0sum = 0.0f, r1sum = 0.0f;
#pragma unroll
        for (int an = 0; an < 8; an++) {
            int cA = an * 8 + 2 * tg;
            float b2a = b2[cA], b2b = b2[cA + 1];
            float w3a = w3[cA], w3b = w3[cA + 1];
            r0sum += fmaxf(acc[am][an][0] + b2a, 0.0f) * w3a
                   + fmaxf(acc[am][an][1] + b2b, 0.0f) * w3b;
            r1sum += fmaxf(acc[am][an][2] + b2a, 0.0f) * w3a
                   + fmaxf(acc[am][an][3] + b2b, 0.0f) * w3b;
        }
        r0sum += __shfl_down_sync(0xffffffffu, r0sum, 2, 4);
        r0sum += __shfl_down_sync(0xffffffffu, r0sum, 1, 4);
        r1sum += __shfl_down_sync(0xffffffffu, r1sum, 2, 4);
        r1sum += __shfl_down_sync(0xffffffffu, r1sum, 1, 4);
        if (tg == 0) {
            int row = r0 + mwarp + am * 16 + gid;
            if (row < EE)     out[row]     = r0sum + b3v;
            if (row + 8 < EE) out[row + 8] = r1sum + b3v;
        }
    }
}

// ---------------- launch ----------------
extern "C" void kernel_launch(void* const* d_in, const int* in_sizes, int n_in,
                              void* d_out, int out_size) {
    const float* x       = (const float*)d_in[0];
    const int*   ei      = (const int*)d_in[1];
    const float* eattr   = (const float*)d_in[2];
    const int*   shock   = (const int*)d_in[3];
    const float* enc_w   = (const float*)d_in[4];
    const float* enc_b   = (const float*)d_in[5];
    const float* enc_lng = (const float*)d_in[6];
    const float* enc_lnb = (const float*)d_in[7];
    const float* gat_w   = (const float*)d_in[8];
    const float* att_src = (const float*)d_in[9];
    const float* att_dst = (const float*)d_in[10];
    const float* gat_bias= (const float*)d_in[11];
    const float* bn_g    = (const float*)d_in[12];
    const float* bn_b    = (const float*)d_in[13];
    const float* bn_m    = (const float*)d_in[14];
    const float* bn_v    = (const float*)d_in[15];
    const float* em1_w   = (const float*)d_in[16];
    const float* em1_b   = (const float*)d_in[17];
    const float* em_lng  = (const float*)d_in[18];
    const float* em_lnb  = (const float*)d_in[19];
    const float* em2_w   = (const float*)d_in[20];
    const float* em2_b   = (const float*)d_in[21];
    const float* em3_w   = (const float*)d_in[22];
    const float* em3_b   = (const float*)d_in[23];
    const int* src = ei;
    const int* dst = ei + EE;
    float* out = (float*)d_out;

    float *ph, *ph2, *pbnsc, *pbnsh;
    __half *paggh, *ppqh, *pwh, *pempq;
    cudaGetSymbolAddress((void**)&ph,    g_h);
    cudaGetSymbolAddress((void**)&ph2,   g_h2);
    cudaGetSymbolAddress((void**)&paggh, g_aggh);
    cudaGetSymbolAddress((void**)&ppqh,  g_pqh);
    cudaGetSymbolAddress((void**)&pwh,   g_wpermh);
    cudaGetSymbolAddress((void**)&pempq, g_empq);
    cudaGetSymbolAddress((void**)&pbnsc, g_bnscale);
    cudaGetSymbolAddress((void**)&pbnsh, g_bnshift);

    // graph prep (encoder at launch #4 for the ncu window)
    k_zero_misc<<<(NN + 255) / 256, 256>>>();
    k_downcount<<<(E2 + 255) / 256, 256>>>(src, dst, shock);
    int nb = (NN + 1023) / 1024;
    k_scan1<<<nb, 1024>>>();
    k_encoder2<<<(NN + 63) / 64, 256>>>(x, shock, enc_w, enc_b, enc_lng, enc_lnb, ph);
    k_scan2<<<1, 64>>>(nb);
    k_scan3<<<(NN + 255) / 256, 256>>>();
    k_scatter<<<(E2 + 255) / 256, 256>>>(src, dst);

    // weight prep
    k_watt<<<dim3(3, 4), 128>>>(gat_w, att_src, att_dst);
    k_permw_h<<<dim3(3, 512), 128>>>(gat_w);
    k_prep_em<<<128, 128>>>(em1_w, em2_w);
    k_bnprep<<<3, 128>>>(gat_bias, bn_g, bn_b, bn_m, bn_v);

    // 3 GAT layers
    float* hin = ph;
    float* hout = ph2;
    int gx = (NN + 127) / 128;
    for (int l = 0; l < 3; l++) {
        k_logits2<<<(NN + 3) / 4, 128>>>(hin, l);
        k_gather2<<<(NN + 3) / 4, 128>>>(hin, paggh);
        gemm_f16<1, 0><<<dim3(gx, 1), 256>>>(paggh, pwh + (size_t)l * 128 * 512, hout, NN, 512,
                                             pbnsc + l * 128, pbnsh + l * 128, (l < 2) ? 1 : 0, 0, 0);
        float* tmp = hin; hin = hout; hout = tmp;
    }

    // p and q in one launch: grid.y selects weight half and output half
    gemm_f16<0, 1><<<dim3(gx, 2), 256>>>(hin, pempq, ppqh, NN, 128, nullptr, nullptr, 0,
                                         128 * 128, (long)NN * HD);

    // edge predictor: LN pass then tensor-core GEMM+reduce
    k_edge_ln<<<EE / 8, 256>>>(src, dst, eattr, em1_b, em1_w + 256 * HD, em_lng, em_lnb);
    k_edge_gemm<<<(EE + 127) / 128, 128>>>(em2_b, em3_w, em3_b, out);
}

// round 16
// speedup vs baseline: 1.5805x; 1.0126x over previous
#include <cuda_runtime.h>
#include <cuda_bf16.h>
#include <cuda_fp16.h>
#include <math.h>
#include <stdint.h>

#define NN 50000
#define EE 200000
#define E2 (EE + NN)
#define HD 128

// ---------------- scratch (static device globals; no allocation) ----------------
__device__ int   g_down[NN];
__device__ __align__(16) float g_h[NN * HD];
__device__ __align__(16) float g_h2[NN * HD];
__device__ __align__(16) __half g_aggh[(size_t)NN * 512];
__device__ __align__(16) float g_als[NN * 4];
__device__ __align__(16) float g_ald[NN * 4];
__device__ int   g_cnt[NN];
__device__ int   g_rowtmp[NN];
__device__ int   g_bsum[64];
__device__ int   g_rowptr[NN + 1];
__device__ int   g_cursor[NN];
__device__ int   g_csrsrc[E2];
__device__ __align__(16) __half g_pqh[2 * (size_t)NN * HD];   // p then q
__device__ __align__(16) __half g_z1[(size_t)(EE + 128) * HD];
__device__ __align__(16) float g_wsrc[3 * 4 * 128];
__device__ __align__(16) float g_wdst[3 * 4 * 128];
__device__ __align__(16) __half g_wpermh[3 * 128 * 512];  // [l][cout][kk]
__device__ __align__(16) __half g_empq[2 * 128 * 128];    // [n][k] p-half then q-half
__device__ __align__(16) __half g_emw2h[64 * 128];        // [n][k]
__device__ __align__(16) float g_bnscale[3 * 128];
__device__ __align__(16) float g_bnshift[3 * 128];

__device__ __forceinline__ uint32_t f22u(float a, float b) {
    __half2 h = __floats2half2_rn(a, b);
    return *(uint32_t*)&h;
}
__device__ __forceinline__ float4 u2tof4(uint2 u) {
    float2 a = __half22float2(*(__half2*)&u.x);
    float2 b = __half22float2(*(__half2*)&u.y);
    return make_float4(a.x, a.y, b.x, b.y);
}

// ---------------- small helpers ----------------
__global__ void k_zero_misc() {
    int i = blockIdx.x * blockDim.x + threadIdx.x;
    if (i < NN) { g_down[i] = 0; g_cnt[i] = 0; }
}

__global__ void k_downcount(const int* __restrict__ src, const int* __restrict__ dst,
                            const int* __restrict__ shock) {
    int e = blockIdx.x * blockDim.x + threadIdx.x;
    if (e >= E2) return;
    if (e < EE) {
        int s = src[e], d = dst[e];
        if (shock[s] != 0) g_down[d] = 1;
        atomicAdd(&g_cnt[d], 1);
    } else {
        atomicAdd(&g_cnt[e - EE], 1);
    }
}

__global__ void k_scan1() {
    __shared__ int sh[1024];
    int tid = threadIdx.x;
    int i = blockIdx.x * 1024 + tid;
    int v = (i < NN) ? g_cnt[i] : 0;
    sh[tid] = v;
    __syncthreads();
    for (int off = 1; off < 1024; off <<= 1) {
        int t = (tid >= off) ? sh[tid - off] : 0;
        __syncthreads();
        sh[tid] += t;
        __syncthreads();
    }
    int incl = sh[tid];
    if (i < NN) g_rowtmp[i] = incl - v;
    if (tid == 1023) g_bsum[blockIdx.x] = incl;
}

__global__ void k_scan2(int nb) {
    __shared__ int sh[64];
    int t = threadIdx.x;
    int v = (t < nb) ? g_bsum[t] : 0;
    sh[t] = v;
    __syncthreads();
    for (int off = 1; off < 64; off <<= 1) {
        int u = (t >= off) ? sh[t - off] : 0;
        __syncthreads();
        sh[t] += u;
        __syncthreads();
    }
    if (t < nb) g_bsum[t] = sh[t] - v;
}

__global__ void k_scan3() {
    int i = blockIdx.x * blockDim.x + threadIdx.x;
    if (i >= NN) return;
    int r = g_rowtmp[i] + g_bsum[i >> 10];
    g_rowptr[i] = r;
    g_cursor[i] = r;
    if (i == NN - 1) g_rowptr[NN] = E2;
}

__global__ void k_scatter(const int* __restrict__ src, const int* __restrict__ dst) {
    int e = blockIdx.x * blockDim.x + threadIdx.x;
    if (e >= E2) return;
    int s, d;
    if (e < EE) { s = src[e]; d = dst[e]; } else { s = e - EE; d = e - EE; }
    int pos = atomicAdd(&g_cursor[d], 1);
    g_csrsrc[pos] = s;
}

// ---------------- node encoder: 64 nodes/block, W in smem, warp-per-node ----
__global__ __launch_bounds__(256) void k_encoder2(
        const float* __restrict__ x, const int* __restrict__ shock,
        const float* __restrict__ W, const float* __restrict__ b,
        const float* __restrict__ lng, const float* __restrict__ lnb,
        float* __restrict__ hout) {
    __shared__ __align__(16) float Ws[18][128];
    __shared__ __align__(16) float bs[128], gs[128], os[128];
    int tid = threadIdx.x;
#pragma unroll
    for (int i = 0; i < 3; i++) {
        int idx = tid + i * 256;
        if (idx < 576) ((float4*)Ws)[idx] = ((const float4*)W)[idx];
    }
    if (tid < 128) { bs[tid] = b[tid]; gs[tid] = lng[tid]; os[tid] = lnb[tid]; }
    __syncthreads();

    int w = tid >> 5, lane = tid & 31;
#pragma unroll
    for (int it = 0; it < 8; it++) {
        int n = blockIdx.x * 64 + it * 8 + w;
        if (n >= NN) continue;
        const float4* xr = (const float4*)(x + n * 16);
        float4 x0 = xr[0], x1 = xr[1], x2 = xr[2], x3 = xr[3];
        float sh_ = (float)shock[n];
        float dn_ = (float)g_down[n];
        float xa[16] = {x0.x, x0.y, x0.z, x0.w, x1.x, x1.y, x1.z, x1.w,
                        x2.x, x2.y, x2.z, x2.w, x3.x, x3.y, x3.z, x3.w};
        int c = lane * 4;
        float4 v = *(const float4*)&bs[c];
#pragma unroll
        for (int j = 0; j < 16; j++) {
            float4 w4 = *(const float4*)&Ws[j][c];
            v.x += xa[j] * w4.x; v.y += xa[j] * w4.y;
            v.z += xa[j] * w4.z; v.w += xa[j] * w4.w;
        }
        {
            float4 w4 = *(const float4*)&Ws[16][c];
            v.x += sh_ * w4.x; v.y += sh_ * w4.y; v.z += sh_ * w4.z; v.w += sh_ * w4.w;
            float4 w5 = *(const float4*)&Ws[17][c];
            v.x += dn_ * w5.x; v.y += dn_ * w5.y; v.z += dn_ * w5.z; v.w += dn_ * w5.w;
        }
        float su = v.x + v.y + v.z + v.w;
        float sq = v.x * v.x + v.y * v.y + v.z * v.z + v.w * v.w;
#pragma unroll
        for (int off = 16; off > 0; off >>= 1) {
            su += __shfl_xor_sync(0xffffffffu, su, off);
            sq += __shfl_xor_sync(0xffffffffu, sq, off);
        }
        float mu = su * (1.0f / HD);
        float var = sq * (1.0f / HD) - mu * mu;
        float rs = rsqrtf(var + 1e-5f);
        float4 g4 = *(const float4*)&gs[c];
        float4 o4 = *(const float4*)&os[c];
        float4 y;
        y.x = fmaxf((v.x - mu) * rs * g4.x + o4.x, 0.0f);
        y.y = fmaxf((v.y - mu) * rs * g4.y + o4.y, 0.0f);
        y.z = fmaxf((v.z - mu) * rs * g4.z + o4.z, 0.0f);
        y.w = fmaxf((v.w - mu) * rs * g4.w + o4.w, 0.0f);
        *(float4*)&hout[(size_t)n * HD + c] = y;
    }
}

// ---------------- weight prep ----------------
__global__ void k_watt(const float* __restrict__ gw,
                       const float* __restrict__ as_, const float* __restrict__ ad_) {
    int l = blockIdx.x, h = blockIdx.y;
    int k = threadIdx.x;
    __shared__ float s_as[128], s_ad[128];
    s_as[k] = as_[(l * 4 + h) * 128 + k];
    s_ad[k] = ad_[(l * 4 + h) * 128 + k];
    __syncthreads();
    const float* wrow = gw + ((size_t)l * 128 + k) * 512 + h * 128;
    float ss = 0.0f, sd = 0.0f;
#pragma unroll 8
    for (int cc = 0; cc < 128; cc++) {
        float w = wrow[cc];
        ss += w * s_as[cc];
        sd += w * s_ad[cc];
    }
    g_wsrc[(l * 4 + h) * 128 + k] = ss;
    g_wdst[(l * 4 + h) * 128 + k] = sd;
}

__global__ void k_permw_h(const float* __restrict__ gw) {
    int l = blockIdx.x;
    int kk = blockIdx.y;
    int cout = threadIdx.x;
    int k_in = kk & 127, hd = kk >> 7;
    float v = 0.25f * gw[((size_t)l * 128 + k_in) * 512 + (hd << 7) + cout];
    g_wpermh[((size_t)l * 128 + cout) * 512 + kk] = __float2half(v);
}

__global__ void k_prep_em(const float* __restrict__ em1w, const float* __restrict__ em2w) {
    int n = blockIdx.x;
    int k = threadIdx.x;
    g_empq[n * 128 + k]             = __float2half(em1w[(size_t)k * 128 + n]);
    g_empq[128 * 128 + n * 128 + k] = __float2half(em1w[(size_t)(128 + k) * 128 + n]);
    if (n < 64) g_emw2h[n * 128 + k] = __float2half(em2w[(size_t)k * 64 + n]);
}

__global__ void k_bnprep(const float* __restrict__ bias, const float* __restrict__ bng,
                         const float* __restrict__ bnb, const float* __restrict__ bnm,
                         const float* __restrict__ bnv) {
    int l = blockIdx.x, c = threadIdx.x;
    int i = l * 128 + c;
    float sc = bng[i] * rsqrtf(bnv[i] + 1e-5f);
    g_bnscale[i] = sc;
    g_bnshift[i] = (bias[i] - bnm[i]) * sc + bnb[i];
}

// ---------------- fp16 tensor-core GEMM: C[M,128] = A[M,K] @ B^T ----------------
// Double-buffered SMEM mainloop (prefetch next chunk to registers during MMA).
__device__ __forceinline__ void mma_f16(float* d, const uint32_t* a, const uint32_t* b) {
    asm volatile(
        "mma.sync.aligned.m16n8k16.row.col.f32.f16.f16.f32 "
        "{%0,%1,%2,%3}, {%4,%5,%6,%7}, {%8,%9}, {%0,%1,%2,%3};\n"
        : "+f"(d[0]), "+f"(d[1]), "+f"(d[2]), "+f"(d[3])
        : "r"(a[0]), "r"(a[1]), "r"(a[2]), "r"(a[3]), "r"(b[0]), "r"(b[1]));
}

template <int AH, int OH>
__global__ __launch_bounds__(256) void gemm_f16(const void* __restrict__ Av,
                                                const __half* __restrict__ B0,
                                                void* __restrict__ Cv,
                                                int M, int K,
                                                const float* __restrict__ escale,
                                                const float* __restrict__ eshift,
                                                int do_relu, long bStride, long cStride) {
    __shared__ __align__(16) __half As[2][128][40];
    __shared__ __align__(16) __half Bs[2][128][40];
    const __half* B = B0 + blockIdx.y * bStride;
    int tid = threadIdx.x;
    int m0 = blockIdx.x * 128;
    int lane = tid & 31, wid = tid >> 5;
    int mbase = (wid & 1) * 64;
    int nbase = (wid >> 1) * 32;
    int gid = lane >> 2, tg = lane & 3;

    float acc[4][4][4];
#pragma unroll
    for (int i = 0; i < 4; i++)
#pragma unroll
        for (int j = 0; j < 4; j++)
#pragma unroll
            for (int q = 0; q < 4; q++) acc[i][j][q] = 0.0f;

    // prologue: chunk 0 -> buffer 0
    if (AH) {
        const __half* A = (const __half*)Av;
#pragma unroll
        for (int i = 0; i < 2; i++) {
            int l4 = tid + i * 256;
            int row = l4 >> 2, c8 = (l4 & 3) << 3;
            uint4 v = make_uint4(0, 0, 0, 0);
            int gr = m0 + row;
            if (gr < M) v = *(const uint4*)&A[(size_t)gr * K + c8];
            *(uint4*)&As[0][row][c8] = v;
        }
    } else {
        const float* A = (const float*)Av;
#pragma unroll
        for (int i = 0; i < 4; i++) {
            int l4 = tid + i * 256;
            int row = l4 >> 3, c4 = (l4 & 7) << 2;
            float4 v = make_float4(0.f, 0.f, 0.f, 0.f);
            int gr = m0 + row;
            if (gr < M) v = *(const float4*)&A[(size_t)gr * K + c4];
            *(__half2*)&As[0][row][c4]     = __floats2half2_rn(v.x, v.y);
            *(__half2*)&As[0][row][c4 + 2] = __floats2half2_rn(v.z, v.w);
        }
    }
#pragma unroll
    for (int i = 0; i < 2; i++) {
        int l = tid + i * 256;
        int n = l >> 2, k8 = (l & 3) << 3;
        *(uint4*)&Bs[0][n][k8] = *(const uint4*)&B[(size_t)n * K + k8];
    }
    __syncthreads();

    int nchunks = K >> 5;
    for (int ic = 0; ic < nchunks; ic++) {
        int cur = ic & 1;
        int kc_next = (ic + 1) << 5;
        uint4 pa_h[2]; float4 pa_f[4]; uint4 pb[2];
        if (ic + 1 < nchunks) {
            if (AH) {
                const __half* A = (const __half*)Av;
#pragma unroll
                for (int i = 0; i < 2; i++) {
                    int l4 = tid + i * 256;
                    int row = l4 >> 2, c8 = (l4 & 3) << 3;
                    pa_h[i] = make_uint4(0, 0, 0, 0);
                    int gr = m0 + row;
                    if (gr < M) pa_h[i] = *(const uint4*)&A[(size_t)gr * K + kc_next + c8];
                }
            } else {
                const float* A = (const float*)Av;
#pragma unroll
                for (int i = 0; i < 4; i++) {
                    int l4 = tid + i * 256;
                    int row = l4 >> 3, c4 = (l4 & 7) << 2;
                    pa_f[i] = make_float4(0.f, 0.f, 0.f, 0.f);
                    int gr = m0 + row;
                    if (gr < M) pa_f[i] = *(const float4*)&A[(size_t)gr * K + kc_next + c4];
                }
            }
#pragma unroll
            for (int i = 0; i < 2; i++) {
                int l = tid + i * 256;
                int n = l >> 2, k8 = (l & 3) << 3;
                pb[i] = *(const uint4*)&B[(size_t)n * K + kc_next + k8];
            }
        }

#pragma unroll
        for (int k0 = 0; k0 < 32; k0 += 16) {
            uint32_t af[4][4], bf[4][2];
#pragma unroll
            for (int am = 0; am < 4; am++) {
                int row0 = mbase + am * 16 + gid;
                af[am][0] = *(const uint32_t*)&As[cur][row0][k0 + tg * 2];
                af[am][1] = *(const uint32_t*)&As[cur][row0 + 8][k0 + tg * 2];
                af[am][2] = *(const uint32_t*)&As[cur][row0][k0 + tg * 2 + 8];
                af[am][3] = *(const uint32_t*)&As[cur][row0 + 8][k0 + tg * 2 + 8];
            }
#pragma unroll
            for (int an = 0; an < 4; an++) {
                int n0 = nbase + an * 8 + gid;
                bf[an][0] = *(const uint32_t*)&Bs[cur][n0][k0 + tg * 2];
                bf[an][1] = *(const uint32_t*)&Bs[cur][n0][k0 + tg * 2 + 8];
            }
#pragma unroll
            for (int am = 0; am < 4; am++)
#pragma unroll
                for (int an = 0; an < 4; an++)
                    mma_f16(acc[am][an], af[am], bf[an]);
        }

        if (ic + 1 < nchunks) {
            __syncthreads();
            int nxt = cur ^ 1;
            if (AH) {
#pragma unroll
                for (int i = 0; i < 2; i++) {
                    int l4 = tid + i * 256;
                    int row = l4 >> 2, c8 = (l4 & 3) << 3;
                    *(uint4*)&As[nxt][row][c8] = pa_h[i];
                }
            } else {
#pragma unroll
                for (int i = 0; i < 4; i++) {
                    int l4 = tid + i * 256;
                    int row = l4 >> 3, c4 = (l4 & 7) << 2;
                    *(__half2*)&As[nxt][row][c4]     = __floats2half2_rn(pa_f[i].x, pa_f[i].y);
                    *(__half2*)&As[nxt][row][c4 + 2] = __floats2half2_rn(pa_f[i].z, pa_f[i].w);
                }
            }
#pragma unroll
            for (int i = 0; i < 2; i++) {
                int l = tid + i * 256;
                int n = l >> 2, k8 = (l & 3) << 3;
                *(uint4*)&Bs[nxt][n][k8] = pb[i];
            }
            __syncthreads();
        }
    }

#pragma unroll
    for (int am = 0; am < 4; am++) {
        int row = m0 + mbase + am * 16 + gid;
#pragma unroll
        for (int an = 0; an < 4; an++) {
            int col = nbase + an * 8 + 2 * tg;
            float v0 = acc[am][an][0], v1 = acc[am][an][1];
            float v2 = acc[am][an][2], v3 = acc[am][an][3];
            if (escale) {
                float s0 = escale[col], s1 = escale[col + 1];
                float h0 = eshift[col], h1 = eshift[col + 1];
                v0 = v0 * s0 + h0; v1 = v1 * s1 + h1;
                v2 = v2 * s0 + h0; v3 = v3 * s1 + h1;
                if (do_relu) {
                    v0 = fmaxf(v0, 0.f); v1 = fmaxf(v1, 0.f);
                    v2 = fmaxf(v2, 0.f); v3 = fmaxf(v3, 0.f);
                }
            }
            if (OH) {
                __half* C = (__half*)Cv + blockIdx.y * cStride;
                if (row < M)     *(uint32_t*)&C[(size_t)row * 128 + col]       = f22u(v0, v1);
                if (row + 8 < M) *(uint32_t*)&C[(size_t)(row + 8) * 128 + col] = f22u(v2, v3);
            } else {
                float* C = (float*)Cv;
                if (row < M)     *(float2*)&C[(size_t)row * 128 + col]       = make_float2(v0, v1);
                if (row + 8 < M) *(float2*)&C[(size_t)(row + 8) * 128 + col] = make_float2(v2, v3);
            }
        }
    }
}

// ---------------- logits from h directly: als = h @ Wa ----------------
__global__ void k_logits2(const float* __restrict__ h, int l) {
    int node = blockIdx.x * 4 + (threadIdx.x >> 5);
    int lane = threadIdx.x & 31;
    if (node >= NN) return;
    float4 hv = *(const float4*)&h[(size_t)node * HD + lane * 4];
#pragma unroll
    for (int hh = 0; hh < 4; hh++) {
        float4 ws = *(const float4*)&g_wsrc[(l * 4 + hh) * 128 + lane * 4];
        float4 wd = *(const float4*)&g_wdst[(l * 4 + hh) * 128 + lane * 4];
        float ds = hv.x * ws.x + hv.y * ws.y + hv.z * ws.z + hv.w * ws.w;
        float dd = hv.x * wd.x + hv.y * wd.y + hv.z * wd.z + hv.w * wd.w;
#pragma unroll
        for (int off = 16; off > 0; off >>= 1) {
            ds += __shfl_down_sync(0xffffffffu, ds, off);
            dd += __shfl_down_sync(0xffffffffu, dd, off);
        }
        if (lane == 0) { g_als[node * 4 + hh] = ds; g_ald[node * 4 + hh] = dd; }
    }
}

// ------- gather: softmax + aggregate h[src] per head -> aggh[N,512] fp16 -------
__global__ void k_gather2(const float* __restrict__ h, __half* __restrict__ aggh) {
    int node = blockIdx.x * 4 + (threadIdx.x >> 5);
    int lane = threadIdx.x & 31;
    if (node >= NN) return;
    int beg = g_rowptr[node], end = g_rowptr[node + 1];
    int deg = end - beg;
    float4 ald4 = *(const float4*)&g_ald[node * 4];

    float4 acc0 = make_float4(0, 0, 0, 0), acc1 = acc0, acc2 = acc0, acc3 = acc0;
    float4 sum = make_float4(0, 0, 0, 0);

    if (deg <= 32) {
        int s = 0;
        float4 a = make_float4(-1e30f, -1e30f, -1e30f, -1e30f);
        if (lane < deg) {
            s = g_csrsrc[beg + lane];
            a = *(const float4*)&g_als[s * 4];
            a.x += ald4.x; a.y += ald4.y; a.z += ald4.z; a.w += ald4.w;
            a.x = (a.x >= 0.f) ? a.x : 0.2f * a.x;
            a.y = (a.y >= 0.f) ? a.y : 0.2f * a.y;
            a.z = (a.z >= 0.f) ? a.z : 0.2f * a.z;
            a.w = (a.w >= 0.f) ? a.w : 0.2f * a.w;
        }
        float4 mx = a;
#pragma unroll
        for (int off = 16; off > 0; off >>= 1) {
            mx.x = fmaxf(mx.x, __shfl_xor_sync(0xffffffffu, mx.x, off));
            mx.y = fmaxf(mx.y, __shfl_xor_sync(0xffffffffu, mx.y, off));
            mx.z = fmaxf(mx.z, __shfl_xor_sync(0xffffffffu, mx.z, off));
            mx.w = fmaxf(mx.w, __shfl_xor_sync(0xffffffffu, mx.w, off));
        }
        float4 w = make_float4(0, 0, 0, 0);
        if (lane < deg) {
            w.x = expf(a.x - mx.x); w.y = expf(a.y - mx.y);
            w.z = expf(a.z - mx.z); w.w = expf(a.w - mx.w);
        }
        sum = w;
#pragma unroll
        for (int off = 16; off > 0; off >>= 1) {
            sum.x += __shfl_xor_sync(0xffffffffu, sum.x, off);
            sum.y += __shfl_xor_sync(0xffffffffu, sum.y, off);
            sum.z += __shfl_xor_sync(0xffffffffu, sum.z, off);
            sum.w += __shfl_xor_sync(0xffffffffu, sum.w, off);
        }
        for (int j = 0; j < deg; j++) {
            int sj  = __shfl_sync(0xffffffffu, s, j);
            float w0 = __shfl_sync(0xffffffffu, w.x, j);
            float w1 = __shfl_sync(0xffffffffu, w.y, j);
            float w2 = __shfl_sync(0xffffffffu, w.z, j);
            float w3 = __shfl_sync(0xffffffffu, w.w, j);
            float4 v = *(const float4*)&h[(size_t)sj * HD + lane * 4];
            acc0.x += w0 * v.x; acc0.y += w0 * v.y; acc0.z += w0 * v.z; acc0.w += w0 * v.w;
            acc1.x += w1 * v.x; acc1.y += w1 * v.y; acc1.z += w1 * v.z; acc1.w += w1 * v.w;
            acc2.x += w2 * v.x; acc2.y += w2 * v.y; acc2.z += w2 * v.z; acc2.w += w2 * v.w;
            acc3.x += w3 * v.x; acc3.y += w3 * v.y; acc3.z += w3 * v.z; acc3.w += w3 * v.w;
        }
    } else {
        float4 mx = make_float4(-1e30f, -1e30f, -1e30f, -1e30f);
        for (int i = beg + lane; i < end; i += 32) {
            int s = g_csrsrc[i];
            float4 a = *(const float4*)&g_als[s * 4];
            a.x += ald4.x; a.y += ald4.y; a.z += ald4.z; a.w += ald4.w;
            a.x = (a.x >= 0.f) ? a.x : 0.2f * a.x;
            a.y = (a.y >= 0.f) ? a.y : 0.2f * a.y;
            a.z = (a.z >= 0.f) ? a.z : 0.2f * a.z;
            a.w = (a.w >= 0.f) ? a.w : 0.2f * a.w;
            mx.x = fmaxf(mx.x, a.x); mx.y = fmaxf(mx.y, a.y);
            mx.z = fmaxf(mx.z, a.z); mx.w = fmaxf(mx.w, a.w);
        }
#pragma unroll
        for (int off = 16; off > 0; off >>= 1) {
            mx.x = fmaxf(mx.x, __shfl_xor_sync(0xffffffffu, mx.x, off));
            mx.y = fmaxf(mx.y, __shfl_xor_sync(0xffffffffu, mx.y, off));
            mx.z = fmaxf(mx.z, __shfl_xor_sync(0xffffffffu, mx.z, off));
            mx.w = fmaxf(mx.w, __shfl_xor_sync(0xffffffffu, mx.w, off));
        }
        for (int i = beg; i < end; i++) {
            int s = g_csrsrc[i];
            float4 a = *(const float4*)&g_als[s * 4];
            a.x += ald4.x; a.y += ald4.y; a.z += ald4.z; a.w += ald4.w;
            a.x = (a.x >= 0.f) ? a.x : 0.2f * a.x;
            a.y = (a.y >= 0.f) ? a.y : 0.2f * a.y;
            a.z = (a.z >= 0.f) ? a.z : 0.2f * a.z;
            a.w = (a.w >= 0.f) ? a.w : 0.2f * a.w;
            float w0 = expf(a.x - mx.x), w1 = expf(a.y - mx.y);
            float w2 = expf(a.z - mx.z), w3 = expf(a.w - mx.w);
            sum.x += w0; sum.y += w1; sum.z += w2; sum.w += w3;
            float4 v = *(const float4*)&h[(size_t)s * HD + lane * 4];
            acc0.x += w0 * v.x; acc0.y += w0 * v.y; acc0.z += w0 * v.z; acc0.w += w0 * v.w;
            acc1.x += w1 * v.x; acc1.y += w1 * v.y; acc1.z += w1 * v.z; acc1.w += w1 * v.w;
            acc2.x += w2 * v.x; acc2.y += w2 * v.y; acc2.z += w2 * v.z; acc2.w += w2 * v.w;
            acc3.x += w3 * v.x; acc3.y += w3 * v.y; acc3.z += w3 * v.z; acc3.w += w3 * v.w;
        }
    }

    float i0 = 1.0f / (sum.x + 1e-16f);
    float i1 = 1.0f / (sum.y + 1e-16f);
    float i2 = 1.0f / (sum.z + 1e-16f);
    float i3 = 1.0f / (sum.w + 1e-16f);
    __half* ap = aggh + (size_t)node * 512 + lane * 4;
    *(uint2*)(ap)       = make_uint2(f22u(acc0.x * i0, acc0.y * i0), f22u(acc0.z * i0, acc0.w * i0));
    *(uint2*)(ap + 128) = make_uint2(f22u(acc1.x * i1, acc1.y * i1), f22u(acc1.z * i1, acc1.w * i1));
    *(uint2*)(ap + 256) = make_uint2(f22u(acc2.x * i2, acc2.y * i2), f22u(acc2.z * i2, acc2.w * i2));
    *(uint2*)(ap + 384) = make_uint2(f22u(acc3.x * i3, acc3.y * i3), f22u(acc3.z * i3, acc3.w * i3));
}

// ------- edge LN: warp per edge, z1 = relu(LN(p[s]+q[d]+ea@Wc+b1)) -> fp16 --------
__global__ __launch_bounds__(256) void k_edge_ln(
        const int* __restrict__ src, const int* __restrict__ dst,
        const float* __restrict__ eattr,
        const float* __restrict__ em1b, const float* __restrict__ wc,
        const float* __restrict__ lng, const float* __restrict__ lnb) {
    __shared__ __align__(16) float wcs[8][128];
    __shared__ __align__(16) float b1s[128], gs[128], os[128];
    int tid = threadIdx.x;
    ((float4*)wcs)[tid] = ((const float4*)wc)[tid];
    if (tid < 128) { b1s[tid] = em1b[tid]; gs[tid] = lng[tid]; os[tid] = lnb[tid]; }
    __syncthreads();

    int w = tid >> 5, lane = tid & 31;
    int e = blockIdx.x * 8 + w;
    int s = src[e], d = dst[e];
    const float4* ep = (const float4*)(eattr + (size_t)e * 8);
    float4 ea0 = ep[0], ea1 = ep[1];
    float ea[8] = {ea0.x, ea0.y, ea0.z, ea0.w, ea1.x, ea1.y, ea1.z, ea1.w};
    int c = lane * 4;

    float4 p4 = u2tof4(*(const uint2*)&g_pqh[(size_t)s * HD + c]);
    float4 q4 = u2tof4(*(const uint2*)&g_pqh[(size_t)NN * HD + (size_t)d * HD + c]);
    float4 b4 = *(const float4*)&b1s[c];
    float4 v;
    v.x = p4.x + q4.x + b4.x;
    v.y = p4.y + q4.y + b4.y;
    v.z = p4.z + q4.z + b4.z;
    v.w = p4.w + q4.w + b4.w;
#pragma unroll
    for (int j = 0; j < 8; j++) {
        float4 w4 = *(const float4*)&wcs[j][c];
        v.x += ea[j] * w4.x; v.y += ea[j] * w4.y;
        v.z += ea[j] * w4.z; v.w += ea[j] * w4.w;
    }
    float su = v.x + v.y + v.z + v.w;
    float sq = v.x * v.x + v.y * v.y + v.z * v.z + v.w * v.w;
#pragma unroll
    for (int off = 16; off > 0; off >>= 1) {
        su += __shfl_xor_sync(0xffffffffu, su, off);
        sq += __shfl_xor_sync(0xffffffffu, sq, off);
    }
    float mu = su * (1.0f / HD);
    float var = sq * (1.0f / HD) - mu * mu;
    float rs = rsqrtf(var + 1e-5f);
    float4 g4 = *(const float4*)&gs[c];
    float4 o4 = *(const float4*)&os[c];
    float y0 = fmaxf((v.x - mu) * rs * g4.x + o4.x, 0.0f);
    float y1 = fmaxf((v.y - mu) * rs * g4.y + o4.y, 0.0f);
    float y2 = fmaxf((v.z - mu) * rs * g4.z + o4.z, 0.0f);
    float y3 = fmaxf((v.w - mu) * rs * g4.w + o4.w, 0.0f);
    *(uint2*)&g_z1[(size_t)e * HD + c] = make_uint2(f22u(y0, y1), f22u(y2, y3));
}

// ------- edge GEMM: out[e] = relu(z1[e]@W2 + b2) . w3 + b3, tensor-core ---------
__global__ __launch_bounds__(128) void k_edge_gemm(
        const float* __restrict__ b2, const float* __restrict__ w3,
        const float* __restrict__ b3, float* __restrict__ out) {
    __shared__ __align__(16) __half z1s[128][136];
    __shared__ __align__(16) __half w2s[64][136];
    int tid = threadIdx.x;
    int r0 = blockIdx.x * 128;
#pragma unroll
    for (int i = 0; i < 16; i++) {
        int idx = tid + i * 128;
        int row = idx >> 4, c8 = (idx & 15) << 3;
        *(uint4*)&z1s[row][c8] = *(const uint4*)&g_z1[(size_t)(r0 + row) * HD + c8];
    }
#pragma unroll
    for (int i = 0; i < 8; i++) {
        int idx = tid + i * 128;
        int row = idx >> 4, c8 = (idx & 15) << 3;
        *(uint4*)&w2s[row][c8] = *(const uint4*)&g_emw2h[(size_t)row * HD + c8];
    }
    __syncthreads();

    int w = tid >> 5, lane = tid & 31;
    int gid = lane >> 2, tg = lane & 3;
    int mwarp = w * 32;

    float acc[2][8][4];
#pragma unroll
    for (int i = 0; i < 2; i++)
#pragma unroll
        for (int j = 0; j < 8; j++)
#pragma unroll
            for (int q = 0; q < 4; q++) acc[i][j][q] = 0.0f;

#pragma unroll
    for (int k0 = 0; k0 < 128; k0 += 16) {
        uint32_t af[2][4], bf[8][2];
#pragma unroll
        for (int am = 0; am < 2; am++) {
            int row0 = mwarp + am * 16 + gid;
            af[am][0] = *(const uint32_t*)&z1s[row0][k0 + tg * 2];
            af[am][1] = *(const uint32_t*)&z1s[row0 + 8][k0 + tg * 2];
            af[am][2] = *(const uint32_t*)&z1s[row0][k0 + tg * 2 + 8];
            af[am][3] = *(const uint32_t*)&z1s[row0 + 8][k0 + tg * 2 + 8];
        }
#pragma unroll
        for (int an = 0; an < 8; an++) {
            int n0 = an * 8 + gid;
            bf[an][0] = *(const uint32_t*)&w2s[n0][k0 + tg * 2];
            bf[an][1] = *(const uint32_t*)&w2s[n0][k0 + tg * 2 + 8];
        }
#pragma unroll
        for (int am = 0; am < 2; am++)
#pragma unroll
            for (int an = 0; an < 8; an++)
                mma_f16(acc[am][an], af[am], bf[an]);
    }

    float b3v = b3[0];
#pragma unroll
    for (int am = 0; am < 2; am++) {
        float r0sum = 0.0f, r1sum = 0.0f;
#pragma unroll
        for (int an = 0; an < 8; an++) {
            int cA = an * 8 + 2 * tg;
            float b2a = b2[cA], b2b = b2[cA + 1];
            float w3a = w3[cA], w3b = w3[cA + 1];
            r0sum += fmaxf(acc[am][an][0] + b2a, 0.0f) * w3a
                   + fmaxf(acc[am][an][1] + b2b, 0.0f) * w3b;
            r1sum += fmaxf(acc[am][an][2] + b2a, 0.0f) * w3a
                   + fmaxf(acc[am][an][3] + b2b, 0.0f) * w3b;
        }
        r0sum += __shfl_down_sync(0xffffffffu, r0sum, 2, 4);
        r0sum += __shfl_down_sync(0xffffffffu, r0sum, 1, 4);
        r1sum += __shfl_down_sync(0xffffffffu, r1sum, 2, 4);
        r1sum += __shfl_down_sync(0xffffffffu, r1sum, 1, 4);
        if (tg == 0) {
            int row = r0 + mwarp + am * 16 + gid;
            if (row < EE)     out[row]     = r0sum + b3v;
            if (row + 8 < EE) out[row + 8] = r1sum + b3v;
        }
    }
}

// ---------------- launch ----------------
extern "C" void kernel_launch(void* const* d_in, const int* in_sizes, int n_in,
                              void* d_out, int out_size) {
    const float* x       = (const float*)d_in[0];
    const int*   ei      = (const int*)d_in[1];
    const float* eattr   = (const float*)d_in[2];
    const int*   shock   = (const int*)d_in[3];
    const float* enc_w   = (const float*)d_in[4];
    const float* enc_b   = (const float*)d_in[5];
    const float* enc_lng = (const float*)d_in[6];
    const float* enc_lnb = (const float*)d_in[7];
    const float* gat_w   = (const float*)d_in[8];
    const float* att_src = (const float*)d_in[9];
    const float* att_dst = (const float*)d_in[10];
    const float* gat_bias= (const float*)d_in[11];
    const float* bn_g    = (const float*)d_in[12];
    const float* bn_b    = (const float*)d_in[13];
    const float* bn_m    = (const float*)d_in[14];
    const float* bn_v    = (const float*)d_in[15];
    const float* em1_w   = (const float*)d_in[16];
    const float* em1_b   = (const float*)d_in[17];
    const float* em_lng  = (const float*)d_in[18];
    const float* em_lnb  = (const float*)d_in[19];
    const float* em2_w   = (const float*)d_in[20];
    const float* em2_b   = (const float*)d_in[21];
    const float* em3_w   = (const float*)d_in[22];
    const float* em3_b   = (const float*)d_in[23];
    const int* src = ei;
    const int* dst = ei + EE;
    float* out = (float*)d_out;

    float *ph, *ph2, *pbnsc, *pbnsh;
    __half *paggh, *ppqh, *pwh, *pempq;
    cudaGetSymbolAddress((void**)&ph,    g_h);
    cudaGetSymbolAddress((void**)&ph2,   g_h2);
    cudaGetSymbolAddress((void**)&paggh, g_aggh);
    cudaGetSymbolAddress((void**)&ppqh,  g_pqh);
    cudaGetSymbolAddress((void**)&pwh,   g_wpermh);
    cudaGetSymbolAddress((void**)&pempq, g_empq);
    cudaGetSymbolAddress((void**)&pbnsc, g_bnscale);
    cudaGetSymbolAddress((void**)&pbnsh, g_bnshift);

    // graph prep (encoder at launch #4 for the ncu window)
    k_zero_misc<<<(NN + 255) / 256, 256>>>();
    k_downcount<<<(E2 + 255) / 256, 256>>>(src, dst, shock);
    int nb = (NN + 1023) / 1024;
    k_scan1<<<nb, 1024>>>();
    k_encoder2<<<(NN + 63) / 64, 256>>>(x, shock, enc_w, enc_b, enc_lng, enc_lnb, ph);
    k_scan2<<<1, 64>>>(nb);
    k_scan3<<<(NN + 255) / 256, 256>>>();
    k_scatter<<<(E2 + 255) / 256, 256>>>(src, dst);

    // weight prep
    k_watt<<<dim3(3, 4), 128>>>(gat_w, att_src, att_dst);
    k_permw_h<<<dim3(3, 512), 128>>>(gat_w);
    k_prep_em<<<128, 128>>>(em1_w, em2_w);
    k_bnprep<<<3, 128>>>(gat_bias, bn_g, bn_b, bn_m, bn_v);

    // 3 GAT layers
    float* hin = ph;
    float* hout = ph2;
    int gx = (NN + 127) / 128;
    for (int l = 0; l < 3; l++) {
        k_logits2<<<(NN + 3) / 4, 128>>>(hin, l);
        k_gather2<<<(NN + 3) / 4, 128>>>(hin, paggh);
        gemm_f16<1, 0><<<dim3(gx, 1), 256>>>(paggh, pwh + (size_t)l * 128 * 512, hout, NN, 512,
                                             pbnsc + l * 128, pbnsh + l * 128, (l < 2) ? 1 : 0, 0, 0);
        float* tmp = hin; hin = hout; hout = tmp;
    }

    // p and q in one launch: grid.y selects weight half and output half
    gemm_f16<0, 1><<<dim3(gx, 2), 256>>>(hin, pempq, ppqh, NN, 128, nullptr, nullptr, 0,
                                         128 * 128, (long)NN * HD);

    // edge predictor: LN pass then tensor-core GEMM+reduce
    k_edge_ln<<<EE / 8, 256>>>(src, dst, eattr, em1_b, em1_w + 256 * HD, em_lng, em_lnb);
    k_edge_gemm<<<(EE + 127) / 128, 128>>>(em2_b, em3_w, em3_b, out);
}

// round 17
// speedup vs baseline: 1.6536x; 1.0462x over previous
#include <cuda_runtime.h>
#include <cuda_bf16.h>
#include <cuda_fp16.h>
#include <math.h>
#include <stdint.h>

#define NN 50000
#define EE 200000
#define E2 (EE + NN)
#define HD 128

// ---------------- scratch (static device globals; no allocation) ----------------
__device__ int   g_down[NN];
__device__ __align__(16) float g_h[NN * HD];
__device__ __align__(16) float g_h2[NN * HD];
__device__ __align__(16) __half g_aggh[(size_t)NN * 512];
__device__ __align__(16) float g_als[NN * 4];
__device__ __align__(16) float g_ald[NN * 4];
__device__ int   g_cnt[NN];
__device__ int   g_rowtmp[NN];
__device__ int   g_bsum[64];
__device__ int   g_rowptr[NN + 1];
__device__ int   g_cursor[NN];
__device__ int   g_csrsrc[E2];
__device__ __align__(16) __half g_pqh[2 * (size_t)NN * HD];   // p then q
__device__ __align__(16) __half g_z1[(size_t)(EE + 128) * HD];
__device__ __align__(16) float g_wsrc[3 * 4 * 128];
__device__ __align__(16) float g_wdst[3 * 4 * 128];
__device__ __align__(16) __half g_wpermh[3 * 128 * 512];  // [l][cout][kk]
__device__ __align__(16) __half g_empq[2 * 128 * 128];    // [n][k] p-half then q-half
__device__ __align__(16) __half g_emw2h[64 * 128];        // [n][k]
__device__ __align__(16) float g_bnscale[3 * 128];
__device__ __align__(16) float g_bnshift[3 * 128];

__device__ __forceinline__ uint32_t f22u(float a, float b) {
    __half2 h = __floats2half2_rn(a, b);
    return *(uint32_t*)&h;
}
__device__ __forceinline__ float4 u2tof4(uint2 u) {
    float2 a = __half22float2(*(__half2*)&u.x);
    float2 b = __half22float2(*(__half2*)&u.y);
    return make_float4(a.x, a.y, b.x, b.y);
}

// ---------------- small helpers ----------------
__global__ void k_zero_misc() {
    int i = blockIdx.x * blockDim.x + threadIdx.x;
    if (i < NN) { g_down[i] = 0; g_cnt[i] = 0; }
}

__global__ void k_downcount(const int* __restrict__ src, const int* __restrict__ dst,
                            const int* __restrict__ shock) {
    int e = blockIdx.x * blockDim.x + threadIdx.x;
    if (e >= E2) return;
    if (e < EE) {
        int s = src[e], d = dst[e];
        if (shock[s] != 0) g_down[d] = 1;
        atomicAdd(&g_cnt[d], 1);
    } else {
        atomicAdd(&g_cnt[e - EE], 1);
    }
}

__global__ void k_scan1() {
    __shared__ int sh[1024];
    int tid = threadIdx.x;
    int i = blockIdx.x * 1024 + tid;
    int v = (i < NN) ? g_cnt[i] : 0;
    sh[tid] = v;
    __syncthreads();
    for (int off = 1; off < 1024; off <<= 1) {
        int t = (tid >= off) ? sh[tid - off] : 0;
        __syncthreads();
        sh[tid] += t;
        __syncthreads();
    }
    int incl = sh[tid];
    if (i < NN) g_rowtmp[i] = incl - v;
    if (tid == 1023) g_bsum[blockIdx.x] = incl;
}

__global__ void k_scan2(int nb) {
    __shared__ int sh[64];
    int t = threadIdx.x;
    int v = (t < nb) ? g_bsum[t] : 0;
    sh[t] = v;
    __syncthreads();
    for (int off = 1; off < 64; off <<= 1) {
        int u = (t >= off) ? sh[t - off] : 0;
        __syncthreads();
        sh[t] += u;
        __syncthreads();
    }
    if (t < nb) g_bsum[t] = sh[t] - v;
}

__global__ void k_scan3() {
    int i = blockIdx.x * blockDim.x + threadIdx.x;
    if (i >= NN) return;
    int r = g_rowtmp[i] + g_bsum[i >> 10];
    g_rowptr[i] = r;
    g_cursor[i] = r;
    if (i == NN - 1) g_rowptr[NN] = E2;
}

__global__ void k_scatter(const int* __restrict__ src, const int* __restrict__ dst) {
    int e = blockIdx.x * blockDim.x + threadIdx.x;
    if (e >= E2) return;
    int s, d;
    if (e < EE) { s = src[e]; d = dst[e]; } else { s = e - EE; d = e - EE; }
    int pos = atomicAdd(&g_cursor[d], 1);
    g_csrsrc[pos] = s;
}

// ---------------- node encoder: 64 nodes/block, W in smem, warp-per-node ----
__global__ __launch_bounds__(256) void k_encoder2(
        const float* __restrict__ x, const int* __restrict__ shock,
        const float* __restrict__ W, const float* __restrict__ b,
        const float* __restrict__ lng, const float* __restrict__ lnb,
        float* __restrict__ hout) {
    __shared__ __align__(16) float Ws[18][128];
    __shared__ __align__(16) float bs[128], gs[128], os[128];
    int tid = threadIdx.x;
#pragma unroll
    for (int i = 0; i < 3; i++) {
        int idx = tid + i * 256;
        if (idx < 576) ((float4*)Ws)[idx] = ((const float4*)W)[idx];
    }
    if (tid < 128) { bs[tid] = b[tid]; gs[tid] = lng[tid]; os[tid] = lnb[tid]; }
    __syncthreads();

    int w = tid >> 5, lane = tid & 31;
#pragma unroll
    for (int it = 0; it < 8; it++) {
        int n = blockIdx.x * 64 + it * 8 + w;
        if (n >= NN) continue;
        const float4* xr = (const float4*)(x + n * 16);
        float4 x0 = xr[0], x1 = xr[1], x2 = xr[2], x3 = xr[3];
        float sh_ = (float)shock[n];
        float dn_ = (float)g_down[n];
        float xa[16] = {x0.x, x0.y, x0.z, x0.w, x1.x, x1.y, x1.z, x1.w,
                        x2.x, x2.y, x2.z, x2.w, x3.x, x3.y, x3.z, x3.w};
        int c = lane * 4;
        float4 v = *(const float4*)&bs[c];
#pragma unroll
        for (int j = 0; j < 16; j++) {
            float4 w4 = *(const float4*)&Ws[j][c];
            v.x += xa[j] * w4.x; v.y += xa[j] * w4.y;
            v.z += xa[j] * w4.z; v.w += xa[j] * w4.w;
        }
        {
            float4 w4 = *(const float4*)&Ws[16][c];
            v.x += sh_ * w4.x; v.y += sh_ * w4.y; v.z += sh_ * w4.z; v.w += sh_ * w4.w;
            float4 w5 = *(const float4*)&Ws[17][c];
            v.x += dn_ * w5.x; v.y += dn_ * w5.y; v.z += dn_ * w5.z; v.w += dn_ * w5.w;
        }
        float su = v.x + v.y + v.z + v.w;
        float sq = v.x * v.x + v.y * v.y + v.z * v.z + v.w * v.w;
#pragma unroll
        for (int off = 16; off > 0; off >>= 1) {
            su += __shfl_xor_sync(0xffffffffu, su, off);
            sq += __shfl_xor_sync(0xffffffffu, sq, off);
        }
        float mu = su * (1.0f / HD);
        float var = sq * (1.0f / HD) - mu * mu;
        float rs = rsqrtf(var + 1e-5f);
        float4 g4 = *(const float4*)&gs[c];
        float4 o4 = *(const float4*)&os[c];
        float4 y;
        y.x = fmaxf((v.x - mu) * rs * g4.x + o4.x, 0.0f);
        y.y = fmaxf((v.y - mu) * rs * g4.y + o4.y, 0.0f);
        y.z = fmaxf((v.z - mu) * rs * g4.z + o4.z, 0.0f);
        y.w = fmaxf((v.w - mu) * rs * g4.w + o4.w, 0.0f);
        *(float4*)&hout[(size_t)n * HD + c] = y;
    }
}

// ---------------- merged weight prep (watt | permw | em | bn) ----------------
// blocks: [0,12) watt, [12,1548) permw, [1548,1676) em, [1676,1679) bn; 128 thr.
__global__ void k_prep_all(const float* __restrict__ gw,
                           const float* __restrict__ as_, const float* __restrict__ ad_,
                           const float* __restrict__ em1w, const float* __restrict__ em2w,
                           const float* __restrict__ bias, const float* __restrict__ bng,
                           const float* __restrict__ bnb, const float* __restrict__ bnm,
                           const float* __restrict__ bnv) {
    int b = blockIdx.x;
    int t = threadIdx.x;
    if (b < 12) {
        __shared__ float s_as[128], s_ad[128];
        int l = b >> 2, h = b & 3;
        s_as[t] = as_[(l * 4 + h) * 128 + t];
        s_ad[t] = ad_[(l * 4 + h) * 128 + t];
        __syncthreads();
        const float* wrow = gw + ((size_t)l * 128 + t) * 512 + h * 128;
        float ss = 0.0f, sd = 0.0f;
#pragma unroll 8
        for (int cc = 0; cc < 128; cc++) {
            float w = wrow[cc];
            ss += w * s_as[cc];
            sd += w * s_ad[cc];
        }
        g_wsrc[(l * 4 + h) * 128 + t] = ss;
        g_wdst[(l * 4 + h) * 128 + t] = sd;
    } else if (b < 1548) {
        int bb = b - 12;
        int l = bb / 512, kk = bb % 512;
        int k_in = kk & 127, hd = kk >> 7;
        float v = 0.25f * gw[((size_t)l * 128 + k_in) * 512 + (hd << 7) + t];
        g_wpermh[((size_t)l * 128 + t) * 512 + kk] = __float2half(v);
    } else if (b < 1676) {
        int n = b - 1548;
        g_empq[n * 128 + t]             = __float2half(em1w[(size_t)t * 128 + n]);
        g_empq[128 * 128 + n * 128 + t] = __float2half(em1w[(size_t)(128 + t) * 128 + n]);
        if (n < 64) g_emw2h[n * 128 + t] = __float2half(em2w[(size_t)t * 64 + n]);
    } else {
        int l = b - 1676;
        int i = l * 128 + t;
        float sc = bng[i] * rsqrtf(bnv[i] + 1e-5f);
        g_bnscale[i] = sc;
        g_bnshift[i] = (bias[i] - bnm[i]) * sc + bnb[i];
    }
}

// ---------------- fp16 tensor-core GEMM: C[M,128] = A[M,K] @ B^T ----------------
// Double-buffered SMEM mainloop (prefetch next chunk to registers during MMA).
__device__ __forceinline__ void mma_f16(float* d, const uint32_t* a, const uint32_t* b) {
    asm volatile(
        "mma.sync.aligned.m16n8k16.row.col.f32.f16.f16.f32 "
        "{%0,%1,%2,%3}, {%4,%5,%6,%7}, {%8,%9}, {%0,%1,%2,%3};\n"
        : "+f"(d[0]), "+f"(d[1]), "+f"(d[2]), "+f"(d[3])
        : "r"(a[0]), "r"(a[1]), "r"(a[2]), "r"(a[3]), "r"(b[0]), "r"(b[1]));
}

template <int AH, int OH>
__global__ __launch_bounds__(256) void gemm_f16(const void* __restrict__ Av,
                                                const __half* __restrict__ B0,
                                                void* __restrict__ Cv,
                                                int M, int K,
                                                const float* __restrict__ escale,
                                                const float* __restrict__ eshift,
                                                int do_relu, long bStride, long cStride) {
    __shared__ __align__(16) __half As[2][128][40];
    __shared__ __align__(16) __half Bs[2][128][40];
    const __half* B = B0 + blockIdx.y * bStride;
    int tid = threadIdx.x;
    int m0 = blockIdx.x * 128;
    int lane = tid & 31, wid = tid >> 5;
    int mbase = (wid & 1) * 64;
    int nbase = (wid >> 1) * 32;
    int gid = lane >> 2, tg = lane & 3;

    float acc[4][4][4];
#pragma unroll
    for (int i = 0; i < 4; i++)
#pragma unroll
        for (int j = 0; j < 4; j++)
#pragma unroll
            for (int q = 0; q < 4; q++) acc[i][j][q] = 0.0f;

    if (AH) {
        const __half* A = (const __half*)Av;
#pragma unroll
        for (int i = 0; i < 2; i++) {
            int l4 = tid + i * 256;
            int row = l4 >> 2, c8 = (l4 & 3) << 3;
            uint4 v = make_uint4(0, 0, 0, 0);
            int gr = m0 + row;
            if (gr < M) v = *(const uint4*)&A[(size_t)gr * K + c8];
            *(uint4*)&As[0][row][c8] = v;
        }
    } else {
        const float* A = (const float*)Av;
#pragma unroll
        for (int i = 0; i < 4; i++) {
            int l4 = tid + i * 256;
            int row = l4 >> 3, c4 = (l4 & 7) << 2;
            float4 v = make_float4(0.f, 0.f, 0.f, 0.f);
            int gr = m0 + row;
            if (gr < M) v = *(const float4*)&A[(size_t)gr * K + c4];
            *(__half2*)&As[0][row][c4]     = __floats2half2_rn(v.x, v.y);
            *(__half2*)&As[0][row][c4 + 2] = __floats2half2_rn(v.z, v.w);
        }
    }
#pragma unroll
    for (int i = 0; i < 2; i++) {
        int l = tid + i * 256;
        int n = l >> 2, k8 = (l & 3) << 3;
        *(uint4*)&Bs[0][n][k8] = *(const uint4*)&B[(size_t)n * K + k8];
    }
    __syncthreads();

    int nchunks = K >> 5;
    for (int ic = 0; ic < nchunks; ic++) {
        int cur = ic & 1;
        int kc_next = (ic + 1) << 5;
        uint4 pa_h[2]; float4 pa_f[4]; uint4 pb[2];
        if (ic + 1 < nchunks) {
            if (AH) {
                const __half* A = (const __half*)Av;
#pragma unroll
                for (int i = 0; i < 2; i++) {
                    int l4 = tid + i * 256;
                    int row = l4 >> 2, c8 = (l4 & 3) << 3;
                    pa_h[i] = make_uint4(0, 0, 0, 0);
                    int gr = m0 + row;
                    if (gr < M) pa_h[i] = *(const uint4*)&A[(size_t)gr * K + kc_next + c8];
                }
            } else {
                const float* A = (const float*)Av;
#pragma unroll
                for (int i = 0; i < 4; i++) {
                    int l4 = tid + i * 256;
                    int row = l4 >> 3, c4 = (l4 & 7) << 2;
                    pa_f[i] = make_float4(0.f, 0.f, 0.f, 0.f);
                    int gr = m0 + row;
                    if (gr < M) pa_f[i] = *(const float4*)&A[(size_t)gr * K + kc_next + c4];
                }
            }
#pragma unroll
            for (int i = 0; i < 2; i++) {
                int l = tid + i * 256;
                int n = l >> 2, k8 = (l & 3) << 3;
                pb[i] = *(const uint4*)&B[(size_t)n * K + kc_next + k8];
            }
        }

#pragma unroll
        for (int k0 = 0; k0 < 32; k0 += 16) {
            uint32_t af[4][4], bf[4][2];
#pragma unroll
            for (int am = 0; am < 4; am++) {
                int row0 = mbase + am * 16 + gid;
                af[am][0] = *(const uint32_t*)&As[cur][row0][k0 + tg * 2];
                af[am][1] = *(const uint32_t*)&As[cur][row0 + 8][k0 + tg * 2];
                af[am][2] = *(const uint32_t*)&As[cur][row0][k0 + tg * 2 + 8];
                af[am][3] = *(const uint32_t*)&As[cur][row0 + 8][k0 + tg * 2 + 8];
            }
#pragma unroll
            for (int an = 0; an < 4; an++) {
                int n0 = nbase + an * 8 + gid;
                bf[an][0] = *(const uint32_t*)&Bs[cur][n0][k0 + tg * 2];
                bf[an][1] = *(const uint32_t*)&Bs[cur][n0][k0 + tg * 2 + 8];
            }
#pragma unroll
            for (int am = 0; am < 4; am++)
#pragma unroll
                for (int an = 0; an < 4; an++)
                    mma_f16(acc[am][an], af[am], bf[an]);
        }

        if (ic + 1 < nchunks) {
            __syncthreads();
            int nxt = cur ^ 1;
            if (AH) {
#pragma unroll
                for (int i = 0; i < 2; i++) {
                    int l4 = tid + i * 256;
                    int row = l4 >> 2, c8 = (l4 & 3) << 3;
                    *(uint4*)&As[nxt][row][c8] = pa_h[i];
                }
            } else {
#pragma unroll
                for (int i = 0; i < 4; i++) {
                    int l4 = tid + i * 256;
                    int row = l4 >> 3, c4 = (l4 & 7) << 2;
                    *(__half2*)&As[nxt][row][c4]     = __floats2half2_rn(pa_f[i].x, pa_f[i].y);
                    *(__half2*)&As[nxt][row][c4 + 2] = __floats2half2_rn(pa_f[i].z, pa_f[i].w);
                }
            }
#pragma unroll
            for (int i = 0; i < 2; i++) {
                int l = tid + i * 256;
                int n = l >> 2, k8 = (l & 3) << 3;
                *(uint4*)&Bs[nxt][n][k8] = pb[i];
            }
            __syncthreads();
        }
    }

#pragma unroll
    for (int am = 0; am < 4; am++) {
        int row = m0 + mbase + am * 16 + gid;
#pragma unroll
        for (int an = 0; an < 4; an++) {
            int col = nbase + an * 8 + 2 * tg;
            float v0 = acc[am][an][0], v1 = acc[am][an][1];
            float v2 = acc[am][an][2], v3 = acc[am][an][3];
            if (escale) {
                float s0 = escale[col], s1 = escale[col + 1];
                float h0 = eshift[col], h1 = eshift[col + 1];
                v0 = v0 * s0 + h0; v1 = v1 * s1 + h1;
                v2 = v2 * s0 + h0; v3 = v3 * s1 + h1;
                if (do_relu) {
                    v0 = fmaxf(v0, 0.f); v1 = fmaxf(v1, 0.f);
                    v2 = fmaxf(v2, 0.f); v3 = fmaxf(v3, 0.f);
                }
            }
            if (OH) {
                __half* C = (__half*)Cv + blockIdx.y * cStride;
                if (row < M)     *(uint32_t*)&C[(size_t)row * 128 + col]       = f22u(v0, v1);
                if (row + 8 < M) *(uint32_t*)&C[(size_t)(row + 8) * 128 + col] = f22u(v2, v3);
            } else {
                float* C = (float*)Cv;
                if (row < M)     *(float2*)&C[(size_t)row * 128 + col]       = make_float2(v0, v1);
                if (row + 8 < M) *(float2*)&C[(size_t)(row + 8) * 128 + col] = make_float2(v2, v3);
            }
        }
    }
}

// ---------------- logits from h directly: als = h @ Wa ----------------
__global__ void k_logits2(const float* __restrict__ h, int l) {
    int node = blockIdx.x * 4 + (threadIdx.x >> 5);
    int lane = threadIdx.x & 31;
    if (node >= NN) return;
    float4 hv = *(const float4*)&h[(size_t)node * HD + lane * 4];
#pragma unroll
    for (int hh = 0; hh < 4; hh++) {
        float4 ws = *(const float4*)&g_wsrc[(l * 4 + hh) * 128 + lane * 4];
        float4 wd = *(const float4*)&g_wdst[(l * 4 + hh) * 128 + lane * 4];
        float ds = hv.x * ws.x + hv.y * ws.y + hv.z * ws.z + hv.w * ws.w;
        float dd = hv.x * wd.x + hv.y * wd.y + hv.z * wd.z + hv.w * wd.w;
#pragma unroll
        for (int off = 16; off > 0; off >>= 1) {
            ds += __shfl_down_sync(0xffffffffu, ds, off);
            dd += __shfl_down_sync(0xffffffffu, dd, off);
        }
        if (lane == 0) { g_als[node * 4 + hh] = ds; g_ald[node * 4 + hh] = dd; }
    }
}

// ------- gather: softmax + aggregate h[src] per head -> aggh[N,512] fp16 -------
__global__ void k_gather2(const float* __restrict__ h, __half* __restrict__ aggh) {
    int node = blockIdx.x * 4 + (threadIdx.x >> 5);
    int lane = threadIdx.x & 31;
    if (node >= NN) return;
    int beg = g_rowptr[node], end = g_rowptr[node + 1];
    int deg = end - beg;
    float4 ald4 = *(const float4*)&g_ald[node * 4];

    float4 acc0 = make_float4(0, 0, 0, 0), acc1 = acc0, acc2 = acc0, acc3 = acc0;
    float4 sum = make_float4(0, 0, 0, 0);

    if (deg <= 32) {
        int s = 0;
        float4 a = make_float4(-1e30f, -1e30f, -1e30f, -1e30f);
        if (lane < deg) {
            s = g_csrsrc[beg + lane];
            a = *(const float4*)&g_als[s * 4];
            a.x += ald4.x; a.y += ald4.y; a.z += ald4.z; a.w += ald4.w;
            a.x = (a.x >= 0.f) ? a.x : 0.2f * a.x;
            a.y = (a.y >= 0.f) ? a.y : 0.2f * a.y;
            a.z = (a.z >= 0.f) ? a.z : 0.2f * a.z;
            a.w = (a.w >= 0.f) ? a.w : 0.2f * a.w;
        }
        float4 mx = a;
#pragma unroll
        for (int off = 16; off > 0; off >>= 1) {
            mx.x = fmaxf(mx.x, __shfl_xor_sync(0xffffffffu, mx.x, off));
            mx.y = fmaxf(mx.y, __shfl_xor_sync(0xffffffffu, mx.y, off));
            mx.z = fmaxf(mx.z, __shfl_xor_sync(0xffffffffu, mx.z, off));
            mx.w = fmaxf(mx.w, __shfl_xor_sync(0xffffffffu, mx.w, off));
        }
        float4 w = make_float4(0, 0, 0, 0);
        if (lane < deg) {
            w.x = expf(a.x - mx.x); w.y = expf(a.y - mx.y);
            w.z = expf(a.z - mx.z); w.w = expf(a.w - mx.w);
        }
        sum = w;
#pragma unroll
        for (int off = 16; off > 0; off >>= 1) {
            sum.x += __shfl_xor_sync(0xffffffffu, sum.x, off);
            sum.y += __shfl_xor_sync(0xffffffffu, sum.y, off);
            sum.z += __shfl_xor_sync(0xffffffffu, sum.z, off);
            sum.w += __shfl_xor_sync(0xffffffffu, sum.w, off);
        }
        // 2-way unrolled accumulate: both loads issue before FMAs (MLP=2)
        int j = 0;
        for (; j + 2 <= deg; j += 2) {
            int sj0 = __shfl_sync(0xffffffffu, s, j);
            int sj1 = __shfl_sync(0xffffffffu, s, j + 1);
            float4 va = *(const float4*)&h[(size_t)sj0 * HD + lane * 4];
            float4 vb = *(const float4*)&h[(size_t)sj1 * HD + lane * 4];
            float a0 = __shfl_sync(0xffffffffu, w.x, j);
            float a1 = __shfl_sync(0xffffffffu, w.y, j);
            float a2 = __shfl_sync(0xffffffffu, w.z, j);
            float a3 = __shfl_sync(0xffffffffu, w.w, j);
            float b0 = __shfl_sync(0xffffffffu, w.x, j + 1);
            float b1 = __shfl_sync(0xffffffffu, w.y, j + 1);
            float b2 = __shfl_sync(0xffffffffu, w.z, j + 1);
            float b3 = __shfl_sync(0xffffffffu, w.w, j + 1);
            acc0.x += a0 * va.x + b0 * vb.x; acc0.y += a0 * va.y + b0 * vb.y;
            acc0.z += a0 * va.z + b0 * vb.z; acc0.w += a0 * va.w + b0 * vb.w;
            acc1.x += a1 * va.x + b1 * vb.x; acc1.y += a1 * va.y + b1 * vb.y;
            acc1.z += a1 * va.z + b1 * vb.z; acc1.w += a1 * va.w + b1 * vb.w;
            acc2.x += a2 * va.x + b2 * vb.x; acc2.y += a2 * va.y + b2 * vb.y;
            acc2.z += a2 * va.z + b2 * vb.z; acc2.w += a2 * va.w + b2 * vb.w;
            acc3.x += a3 * va.x + b3 * vb.x; acc3.y += a3 * va.y + b3 * vb.y;
            acc3.z += a3 * va.z + b3 * vb.z; acc3.w += a3 * va.w + b3 * vb.w;
        }
        if (j < deg) {
            int sj = __shfl_sync(0xffffffffu, s, j);
            float a0 = __shfl_sync(0xffffffffu, w.x, j);
            float a1 = __shfl_sync(0xffffffffu, w.y, j);
            float a2 = __shfl_sync(0xffffffffu, w.z, j);
            float a3 = __shfl_sync(0xffffffffu, w.w, j);
            float4 v = *(const float4*)&h[(size_t)sj * HD + lane * 4];
            acc0.x += a0 * v.x; acc0.y += a0 * v.y; acc0.z += a0 * v.z; acc0.w += a0 * v.w;
            acc1.x += a1 * v.x; acc1.y += a1 * v.y; acc1.z += a1 * v.z; acc1.w += a1 * v.w;
            acc2.x += a2 * v.x; acc2.y += a2 * v.y; acc2.z += a2 * v.z; acc2.w += a2 * v.w;
            acc3.x += a3 * v.x; acc3.y += a3 * v.y; acc3.z += a3 * v.z; acc3.w += a3 * v.w;
        }
    } else {
        float4 mx = make_float4(-1e30f, -1e30f, -1e30f, -1e30f);
        for (int i = beg + lane; i < end; i += 32) {
            int s = g_csrsrc[i];
            float4 a = *(const float4*)&g_als[s * 4];
            a.x += ald4.x; a.y += ald4.y; a.z += ald4.z; a.w += ald4.w;
            a.x = (a.x >= 0.f) ? a.x : 0.2f * a.x;
            a.y = (a.y >= 0.f) ? a.y : 0.2f * a.y;
            a.z = (a.z >= 0.f) ? a.z : 0.2f * a.z;
            a.w = (a.w >= 0.f) ? a.w : 0.2f * a.w;
            mx.x = fmaxf(mx.x, a.x); mx.y = fmaxf(mx.y, a.y);
            mx.z = fmaxf(mx.z, a.z); mx.w = fmaxf(mx.w, a.w);
        }
#pragma unroll
        for (int off = 16; off > 0; off >>= 1) {
            mx.x = fmaxf(mx.x, __shfl_xor_sync(0xffffffffu, mx.x, off));
            mx.y = fmaxf(mx.y, __shfl_xor_sync(0xffffffffu, mx.y, off));
            mx.z = fmaxf(mx.z, __shfl_xor_sync(0xffffffffu, mx.z, off));
            mx.w = fmaxf(mx.w, __shfl_xor_sync(0xffffffffu, mx.w, off));
        }
        for (int i = beg; i < end; i++) {
            int s = g_csrsrc[i];
            float4 a = *(const float4*)&g_als[s * 4];
            a.x += ald4.x; a.y += ald4.y; a.z += ald4.z; a.w += ald4.w;
            a.x = (a.x >= 0.f) ? a.x : 0.2f * a.x;
            a.y = (a.y >= 0.f) ? a.y : 0.2f * a.y;
            a.z = (a.z >= 0.f) ? a.z : 0.2f * a.z;
            a.w = (a.w >= 0.f) ? a.w : 0.2f * a.w;
            float w0 = expf(a.x - mx.x), w1 = expf(a.y - mx.y);
            float w2 = expf(a.z - mx.z), w3 = expf(a.w - mx.w);
            sum.x += w0; sum.y += w1; sum.z += w2; sum.w += w3;
            float4 v = *(const float4*)&h[(size_t)s * HD + lane * 4];
            acc0.x += w0 * v.x; acc0.y += w0 * v.y; acc0.z += w0 * v.z; acc0.w += w0 * v.w;
            acc1.x += w1 * v.x; acc1.y += w1 * v.y; acc1.z += w1 * v.z; acc1.w += w1 * v.w;
            acc2.x += w2 * v.x; acc2.y += w2 * v.y; acc2.z += w2 * v.z; acc2.w += w2 * v.w;
            acc3.x += w3 * v.x; acc3.y += w3 * v.y; acc3.z += w3 * v.z; acc3.w += w3 * v.w;
        }
    }

    float i0 = 1.0f / (sum.x + 1e-16f);
    float i1 = 1.0f / (sum.y + 1e-16f);
    float i2 = 1.0f / (sum.z + 1e-16f);
    float i3 = 1.0f / (sum.w + 1e-16f);
    __half* ap = aggh + (size_t)node * 512 + lane * 4;
    *(uint2*)(ap)       = make_uint2(f22u(acc0.x * i0, acc0.y * i0), f22u(acc0.z * i0, acc0.w * i0));
    *(uint2*)(ap + 128) = make_uint2(f22u(acc1.x * i1, acc1.y * i1), f22u(acc1.z * i1, acc1.w * i1));
    *(uint2*)(ap + 256) = make_uint2(f22u(acc2.x * i2, acc2.y * i2), f22u(acc2.z * i2, acc2.w * i2));
    *(uint2*)(ap + 384) = make_uint2(f22u(acc3.x * i3, acc3.y * i3), f22u(acc3.z * i3, acc3.w * i3));
}

// ------- edge LN: 32 edges/block (4 per warp), z1 = relu(LN(p[s]+q[d]+ea@Wc+b1)) -> fp16
__global__ __launch_bounds__(256) void k_edge_ln(
        const int* __restrict__ src, const int* __restrict__ dst,
        const float* __restrict__ eattr,
        const float* __restrict__ em1b, const float* __restrict__ wc,
        const float* __restrict__ lng, const float* __restrict__ lnb) {
    __shared__ __align__(16) float wcs[8][128];
    __shared__ __align__(16) float b1s[128], gs[128], os[128];
    int tid = threadIdx.x;
    ((float4*)wcs)[tid] = ((const float4*)wc)[tid];
    if (tid < 128) { b1s[tid] = em1b[tid]; gs[tid] = lng[tid]; os[tid] = lnb[tid]; }
    __syncthreads();

    int w = tid >> 5, lane = tid & 31;
    int c = lane * 4;
    float4 b4 = *(const float4*)&b1s[c];
    float4 g4 = *(const float4*)&gs[c];
    float4 o4 = *(const float4*)&os[c];

#pragma unroll
    for (int it = 0; it < 4; it++) {
        int e = blockIdx.x * 32 + it * 8 + w;
        int s = src[e], d = dst[e];
        const float4* ep = (const float4*)(eattr + (size_t)e * 8);
        float4 ea0 = ep[0], ea1 = ep[1];
        float ea[8] = {ea0.x, ea0.y, ea0.z, ea0.w, ea1.x, ea1.y, ea1.z, ea1.w};

        float4 p4 = u2tof4(*(const uint2*)&g_pqh[(size_t)s * HD + c]);
        float4 q4 = u2tof4(*(const uint2*)&g_pqh[(size_t)NN * HD + (size_t)d * HD + c]);
        float4 v;
        v.x = p4.x + q4.x + b4.x;
        v.y = p4.y + q4.y + b4.y;
        v.z = p4.z + q4.z + b4.z;
        v.w = p4.w + q4.w + b4.w;
#pragma unroll
        for (int j = 0; j < 8; j++) {
            float4 w4 = *(const float4*)&wcs[j][c];
            v.x += ea[j] * w4.x; v.y += ea[j] * w4.y;
            v.z += ea[j] * w4.z; v.w += ea[j] * w4.w;
        }
        float su = v.x + v.y + v.z + v.w;
        float sq = v.x * v.x + v.y * v.y + v.z * v.z + v.w * v.w;
#pragma unroll
        for (int off = 16; off > 0; off >>= 1) {
            su += __shfl_xor_sync(0xffffffffu, su, off);
            sq += __shfl_xor_sync(0xffffffffu, sq, off);
        }
        float mu = su * (1.0f / HD);
        float var = sq * (1.0f / HD) - mu * mu;
        float rs = rsqrtf(var + 1e-5f);
        float y0 = fmaxf((v.x - mu) * rs * g4.x + o4.x, 0.0f);
        float y1 = fmaxf((v.y - mu) * rs * g4.y + o4.y, 0.0f);
        float y2 = fmaxf((v.z - mu) * rs * g4.z + o4.z, 0.0f);
        float y3 = fmaxf((v.w - mu) * rs * g4.w + o4.w, 0.0f);
        *(uint2*)&g_z1[(size_t)e * HD + c] = make_uint2(f22u(y0, y1), f22u(y2, y3));
    }
}

// ------- edge GEMM: out[e] = relu(z1[e]@W2 + b2) . w3 + b3, tensor-core ---------
__global__ __launch_bounds__(128) void k_edge_gemm(
        const float* __restrict__ b2, const float* __restrict__ w3,
        const float* __restrict__ b3, float* __restrict__ out) {
    __shared__ __align__(16) __half z1s[128][136];
    __shared__ __align__(16) __half w2s[64][136];
    int tid = threadIdx.x;
    int r0 = blockIdx.x * 128;
#pragma unroll
    for (int i = 0; i < 16; i++) {
        int idx = tid + i * 128;
        int row = idx >> 4, c8 = (idx & 15) << 3;
        *(uint4*)&z1s[row][c8] = *(const uint4*)&g_z1[(size_t)(r0 + row) * HD + c8];
    }
#pragma unroll
    for (int i = 0; i < 8; i++) {
        int idx = tid + i * 128;
        int row = idx >> 4, c8 = (idx & 15) << 3;
        *(uint4*)&w2s[row][c8] = *(const uint4*)&g_emw2h[(size_t)row * HD + c8];
    }
    __syncthreads();

    int w = tid >> 5, lane = tid & 31;
    int gid = lane >> 2, tg = lane & 3;
    int mwarp = w * 32;

    float acc[2][8][4];
#pragma unroll
    for (int i = 0; i < 2; i++)
#pragma unroll
        for (int j = 0; j < 8; j++)
#pragma unroll
            for (int q = 0; q < 4; q++) acc[i][j][q] = 0.0f;

#pragma unroll
    for (int k0 = 0; k0 < 128; k0 += 16) {
        uint32_t af[2][4], bf[8][2];
#pragma unroll
        for (int am = 0; am < 2; am++) {
            int row0 = mwarp + am * 16 + gid;
            af[am][0] = *(const uint32_t*)&z1s[row0][k0 + tg * 2];
            af[am][1] = *(const uint32_t*)&z1s[row0 + 8][k0 + tg * 2];
            af[am][2] = *(const uint32_t*)&z1s[row0][k0 + tg * 2 + 8];
            af[am][3] = *(const uint32_t*)&z1s[row0 + 8][k0 + tg * 2 + 8];
        }
#pragma unroll
        for (int an = 0; an < 8; an++) {
            int n0 = an * 8 + gid;
            bf[an][0] = *(const uint32_t*)&w2s[n0][k0 + tg * 2];
            bf[an][1] = *(const uint32_t*)&w2s[n0][k0 + tg * 2 + 8];
        }
#pragma unroll
        for (int am = 0; am < 2; am++)
#pragma unroll
            for (int an = 0; an < 8; an++)
                mma_f16(acc[am][an], af[am], bf[an]);
    }

    float b3v = b3[0];
#pragma unroll
    for (int am = 0; am < 2; am++) {
        float r0sum = 0.0f, r1sum = 0.0f;
#pragma unroll
        for (int an = 0; an < 8; an++) {
            int cA = an * 8 + 2 * tg;
            float b2a = b2[cA], b2b = b2[cA + 1];
            float w3a = w3[cA], w3b = w3[cA + 1];
            r0sum += fmaxf(acc[am][an][0] + b2a, 0.0f) * w3a
                   + fmaxf(acc[am][an][1] + b2b, 0.0f) * w3b;
            r1sum += fmaxf(acc[am][an][2] + b2a, 0.0f) * w3a
                   + fmaxf(acc[am][an][3] + b2b, 0.0f) * w3b;
        }
        r0sum += __shfl_down_sync(0xffffffffu, r0sum, 2, 4);
        r0sum += __shfl_down_sync(0xffffffffu, r0sum, 1, 4);
        r1sum += __shfl_down_sync(0xffffffffu, r1sum, 2, 4);
        r1sum += __shfl_down_sync(0xffffffffu, r1sum, 1, 4);
        if (tg == 0) {
            int row = r0 + mwarp + am * 16 + gid;
            if (row < EE)     out[row]     = r0sum + b3v;
            if (row + 8 < EE) out[row + 8] = r1sum + b3v;
        }
    }
}

// ---------------- launch ----------------
extern "C" void kernel_launch(void* const* d_in, const int* in_sizes, int n_in,
                              void* d_out, int out_size) {
    const float* x       = (const float*)d_in[0];
    const int*   ei      = (const int*)d_in[1];
    const float* eattr   = (const float*)d_in[2];
    const int*   shock   = (const int*)d_in[3];
    const float* enc_w   = (const float*)d_in[4];
    const float* enc_b   = (const float*)d_in[5];
    const float* enc_lng = (const float*)d_in[6];
    const float* enc_lnb = (const float*)d_in[7];
    const float* gat_w   = (const float*)d_in[8];
    const float* att_src = (const float*)d_in[9];
    const float* att_dst = (const float*)d_in[10];
    const float* gat_bias= (const float*)d_in[11];
    const float* bn_g    = (const float*)d_in[12];
    const float* bn_b    = (const float*)d_in[13];
    const float* bn_m    = (const float*)d_in[14];
    const float* bn_v    = (const float*)d_in[15];
    const float* em1_w   = (const float*)d_in[16];
    const float* em1_b   = (const float*)d_in[17];
    const float* em_lng  = (const float*)d_in[18];
    const float* em_lnb  = (const float*)d_in[19];
    const float* em2_w   = (const float*)d_in[20];
    const float* em2_b   = (const float*)d_in[21];
    const float* em3_w   = (const float*)d_in[22];
    const float* em3_b   = (const float*)d_in[23];
    const int* src = ei;
    const int* dst = ei + EE;
    float* out = (float*)d_out;

    float *ph, *ph2, *pbnsc, *pbnsh;
    __half *paggh, *ppqh, *pwh, *pempq;
    cudaGetSymbolAddress((void**)&ph,    g_h);
    cudaGetSymbolAddress((void**)&ph2,   g_h2);
    cudaGetSymbolAddress((void**)&paggh, g_aggh);
    cudaGetSymbolAddress((void**)&ppqh,  g_pqh);
    cudaGetSymbolAddress((void**)&pwh,   g_wpermh);
    cudaGetSymbolAddress((void**)&pempq, g_empq);
    cudaGetSymbolAddress((void**)&pbnsc, g_bnscale);
    cudaGetSymbolAddress((void**)&pbnsh, g_bnshift);

    // graph prep (encoder at launch #4 for the ncu window)
    k_zero_misc<<<(NN + 255) / 256, 256>>>();
    k_downcount<<<(E2 + 255) / 256, 256>>>(src, dst, shock);
    int nb = (NN + 1023) / 1024;
    k_scan1<<<nb, 1024>>>();
    k_encoder2<<<(NN + 63) / 64, 256>>>(x, shock, enc_w, enc_b, enc_lng, enc_lnb, ph);
    k_scan2<<<1, 64>>>(nb);
    k_scan3<<<(NN + 255) / 256, 256>>>();
    k_scatter<<<(E2 + 255) / 256, 256>>>(src, dst);

    // merged weight prep
    k_prep_all<<<1679, 128>>>(gat_w, att_src, att_dst, em1_w, em2_w,
                              gat_bias, bn_g, bn_b, bn_m, bn_v);

    // 3 GAT layers
    float* hin = ph;
    float* hout = ph2;
    int gx = (NN + 127) / 128;
    for (int l = 0; l < 3; l++) {
        k_logits2<<<(NN + 3) / 4, 128>>>(hin, l);
        k_gather2<<<(NN + 3) / 4, 128>>>(hin, paggh);
        gemm_f16<1, 0><<<dim3(gx, 1), 256>>>(paggh, pwh + (size_t)l * 128 * 512, hout, NN, 512,
                                             pbnsc + l * 128, pbnsh + l * 128, (l < 2) ? 1 : 0, 0, 0);
        float* tmp = hin; hin = hout; hout = tmp;
    }

    // p and q in one launch: grid.y selects weight half and output half
    gemm_f16<0, 1><<<dim3(gx, 2), 256>>>(hin, pempq, ppqh, NN, 128, nullptr, nullptr, 0,
                                         128 * 128, (long)NN * HD);

    // edge predictor: LN pass (32 edges/block) then tensor-core GEMM+reduce
    k_edge_ln<<<EE / 32, 256>>>(src, dst, eattr, em1_b, em1_w + 256 * HD, em_lng, em_lnb);
    k_edge_gemm<<<(EE + 127) / 128, 128>>>(em2_b, em3_w, em3_b, out);
}